// round 7
// baseline (speedup 1.0000x reference)
#include <cuda_runtime.h>
#include <cstdint>
#include <cstddef>

// ---------------------------------------------------------------------------
// Problem constants (match reference_code)
// ---------------------------------------------------------------------------
static constexpr int NMAX = 50000;    // nodes
static constexpr int EMAX = 850000;   // edges (800k random + 50k self loops)

// ---------------------------------------------------------------------------
// Scratch (static __device__ globals — no allocation allowed)
// ---------------------------------------------------------------------------
static __device__ __align__(16) float g_h[(size_t)NMAX * 128];     // pre-agg features
static __device__ __align__(16) float g_feat[(size_t)NMAX * 128];  // post-layer features
static __device__ float g_asrc[(size_t)NMAX * 2];
static __device__ float g_adst[(size_t)NMAX * 2];
static __device__ int   g_deg[NMAX];                 // histogram, then cursor
static __device__ int   g_rowstart[NMAX + 1];
static __device__ int   g_csrc[EMAX];                // src sorted by dst
static __device__ int   g_eid[EMAX];                 // original edge id
static __device__ float g_cnt[16];
static __device__ int   g_is64;                      // 1 if index buffers are int64
// fallback scratch if d_out is smaller than the full flattened tuple
static __device__ __align__(16) float g_embS[(size_t)NMAX * 16];
static __device__ __align__(16) float g_alphaS[(size_t)EMAX * 2];
static __device__ float g_gembS[256];

// ---------------------------------------------------------------------------
// Index width detection + decode. Index buffers may be int32 or int64
// (little-endian, values < 2^31). We always address them as 32-bit words.
// ---------------------------------------------------------------------------
__global__ void k_detect_width(const int* __restrict__ w) {
    // For int64 data, odd words are high halves == 0 (values < 50000).
    // For int32 data, odd words are random edge endpoints (~0 prob all zero).
    int z = 0;
#pragma unroll
    for (int k = 0; k < 8; k++) z |= w[2 * k + 1];
    g_is64 = (z == 0) ? 1 : 0;
}

__device__ __forceinline__ int load_idx(const int* __restrict__ w, size_t i) {
    return g_is64 ? w[2 * i] : w[i];
}

// ---------------------------------------------------------------------------
// CSR build
// ---------------------------------------------------------------------------
__global__ void k_zero_deg(int n) {
    int i = blockIdx.x * blockDim.x + threadIdx.x;
    if (i < n) g_deg[i] = 0;
}

__global__ void k_hist(const int* __restrict__ ei, int E, int n) {
    int e = blockIdx.x * blockDim.x + threadIdx.x;
    if (e >= E) return;
    int d = load_idx(ei, (size_t)E + e);
    d = d < 0 ? 0 : (d >= n ? n - 1 : d);
    atomicAdd(&g_deg[d], 1);
}

// single-block exclusive scan over g_deg -> g_rowstart ; zeroes g_deg (cursor)
__global__ void k_scan(int n) {
    __shared__ int sh[1024];
    __shared__ int carry;
    int t = threadIdx.x;
    if (t == 0) carry = 0;
    __syncthreads();
    for (int base = 0; base < n; base += 1024) {
        int i = base + t;
        int v = (i < n) ? g_deg[i] : 0;
        if (i < n) g_deg[i] = 0;
        sh[t] = v;
        __syncthreads();
        for (int off = 1; off < 1024; off <<= 1) {
            int tv = (t >= off) ? sh[t - off] : 0;
            __syncthreads();
            sh[t] += tv;
            __syncthreads();
        }
        if (i < n) g_rowstart[i] = carry + sh[t] - v;
        __syncthreads();
        if (t == 0) carry += sh[1023];
        __syncthreads();
    }
    if (t == 0) g_rowstart[n] = carry;
}

__global__ void k_scatter(const int* __restrict__ ei, int E, int n) {
    int e = blockIdx.x * blockDim.x + threadIdx.x;
    if (e >= E) return;
    int d = load_idx(ei, (size_t)E + e);
    d = d < 0 ? 0 : (d >= n ? n - 1 : d);
    int s = load_idx(ei, (size_t)e);
    s = s < 0 ? 0 : (s >= n ? n - 1 : s);
    int pos = g_rowstart[d] + atomicAdd(&g_deg[d], 1);
    if (pos < EMAX) { g_csrc[pos] = s; g_eid[pos] = e; }
}

// ---------------------------------------------------------------------------
// GEMM: C[n, c] = sum_k A[n,k] * B[k,c], K = 128, COLS = 128
// BM=64, BN=64, BK=16, 256 threads, 4x4 micro-tile, float4 smem traffic.
// ---------------------------------------------------------------------------
template <int COLS>
__global__ void k_gemm64(const float* __restrict__ A, const float* __restrict__ B,
                         float* __restrict__ Cm, int nrows) {
    __shared__ float Ast[16][68];  // transposed A tile [k][m]
    __shared__ float Bs[16][68];
    const int tid = threadIdx.x;
    const int n0 = blockIdx.x * 64;
    const int c0 = blockIdx.y * 64;
    const int tx = tid & 15, ty = tid >> 4;
    const int arow = tid >> 2, akq = (tid & 3) << 2;
    const int bk = tid >> 4, bcq = (tid & 15) << 2;
    const int gr = n0 + arow;

    float a00=0,a01=0,a02=0,a03=0, a10=0,a11=0,a12=0,a13=0,
          a20=0,a21=0,a22=0,a23=0, a30=0,a31=0,a32=0,a33=0;

    for (int kt = 0; kt < 128; kt += 16) {
        float4 av = make_float4(0.f, 0.f, 0.f, 0.f);
        if (gr < nrows) av = *(const float4*)(A + (size_t)gr * 128 + kt + akq);
        float4 bv = *(const float4*)(B + (size_t)(kt + bk) * COLS + c0 + bcq);
        __syncthreads();
        Ast[akq + 0][arow] = av.x;
        Ast[akq + 1][arow] = av.y;
        Ast[akq + 2][arow] = av.z;
        Ast[akq + 3][arow] = av.w;
        *(float4*)(&Bs[bk][bcq]) = bv;
        __syncthreads();
#pragma unroll
        for (int k = 0; k < 16; k++) {
            float4 a = *(const float4*)(&Ast[k][ty << 2]);
            float4 b = *(const float4*)(&Bs[k][tx << 2]);
            a00 += a.x*b.x; a01 += a.x*b.y; a02 += a.x*b.z; a03 += a.x*b.w;
            a10 += a.y*b.x; a11 += a.y*b.y; a12 += a.y*b.z; a13 += a.y*b.w;
            a20 += a.z*b.x; a21 += a.z*b.y; a22 += a.z*b.z; a23 += a.z*b.w;
            a30 += a.w*b.x; a31 += a.w*b.y; a32 += a.w*b.z; a33 += a.w*b.w;
        }
    }
    const int rbase = n0 + (ty << 2);
    const int cbase = c0 + (tx << 2);
    if (rbase + 0 < nrows) { float4 v = {a00,a01,a02,a03}; *(float4*)(Cm + (size_t)(rbase+0)*COLS + cbase) = v; }
    if (rbase + 1 < nrows) { float4 v = {a10,a11,a12,a13}; *(float4*)(Cm + (size_t)(rbase+1)*COLS + cbase) = v; }
    if (rbase + 2 < nrows) { float4 v = {a20,a21,a22,a23}; *(float4*)(Cm + (size_t)(rbase+2)*COLS + cbase) = v; }
    if (rbase + 3 < nrows) { float4 v = {a30,a31,a32,a33}; *(float4*)(Cm + (size_t)(rbase+3)*COLS + cbase) = v; }
}

// Small GEMM for layer 3: [N,128] @ [128,16]
__global__ void k_gemm16(const float* __restrict__ A, const float* __restrict__ B,
                         float* __restrict__ Cm, int nrows) {
    __shared__ float Bs[128 * 16];
    for (int i = threadIdx.x; i < 128 * 16; i += blockDim.x) Bs[i] = B[i];
    __syncthreads();
    int idx = blockIdx.x * blockDim.x + threadIdx.x;
    int n = idx >> 4, c = idx & 15;
    if (n >= nrows) return;
    const float* a = A + (size_t)n * 128;
    float s = 0.f;
#pragma unroll
    for (int k = 0; k < 128; k++) s += a[k] * Bs[k * 16 + c];
    Cm[(size_t)n * 16 + c] = s;
}

// ---------------------------------------------------------------------------
// alpha_src / alpha_dst: one warp per (node, head)
// ---------------------------------------------------------------------------
template <int H, int C>
__global__ void k_alpha(const float* __restrict__ hbuf, const float* __restrict__ avs,
                        const float* __restrict__ avd, int nnodes) {
    int warp = (blockIdx.x * blockDim.x + threadIdx.x) >> 5;
    int lane = threadIdx.x & 31;
    if (warp >= nnodes * H) return;
    int hh = warp % H;
    const float* row = hbuf + (size_t)warp * C;
    float ss = 0.f, sd = 0.f;
    for (int c = lane; c < C; c += 32) {
        float v = row[c];
        ss += v * avs[hh * C + c];
        sd += v * avd[hh * C + c];
    }
#pragma unroll
    for (int o = 16; o; o >>= 1) {
        ss += __shfl_xor_sync(0xffffffffu, ss, o);
        sd += __shfl_xor_sync(0xffffffffu, sd, o);
    }
    if (lane == 0) { g_asrc[warp] = ss; g_adst[warp] = sd; }
}

// ---------------------------------------------------------------------------
// Fused per-node softmax + aggregation (gather over dst-CSR). One warp/node.
// ---------------------------------------------------------------------------
template <int H, int C, bool RELU>
__global__ void k_aggregate(const float* __restrict__ hbuf, const float* __restrict__ bias,
                            float* __restrict__ outbuf, float* __restrict__ alpha_out,
                            int nnodes, int nedges) {
    constexpr int HC = H * C;
    constexpr int PL = (HC + 31) / 32;
    const int warp = (blockIdx.x * blockDim.x + threadIdx.x) >> 5;
    const int lane = threadIdx.x & 31;
    if (warp >= nnodes) return;
    const int n = warp;
    const int s0 = g_rowstart[n];
    const int s1 = g_rowstart[n + 1];

    const float ad0 = g_adst[n * H];
    const float ad1 = (H == 2) ? g_adst[n * H + 1] : 0.f;

    // pass 1: segment max of leaky logits
    float m0 = -1e30f, m1 = -1e30f;
    for (int i = s0 + lane; i < s1; i += 32) {
        int s = g_csrc[i];
        float l0 = g_asrc[s * H] + ad0; l0 = l0 > 0.f ? l0 : 0.2f * l0;
        m0 = fmaxf(m0, l0);
        if (H == 2) {
            float l1 = g_asrc[s * H + 1] + ad1; l1 = l1 > 0.f ? l1 : 0.2f * l1;
            m1 = fmaxf(m1, l1);
        }
    }
#pragma unroll
    for (int o = 16; o; o >>= 1) {
        m0 = fmaxf(m0, __shfl_xor_sync(0xffffffffu, m0, o));
        if (H == 2) m1 = fmaxf(m1, __shfl_xor_sync(0xffffffffu, m1, o));
    }

    // pass 2: sum of exps + unnormalized message accumulation
    float sm0 = 0.f, sm1 = 0.f;
    float acc[PL];
#pragma unroll
    for (int j = 0; j < PL; j++) acc[j] = 0.f;

    for (int base = s0; base < s1; base += 32) {
        int i = base + lane;
        int sv = 0; float w0 = 0.f, w1 = 0.f;
        if (i < s1) {
            sv = g_csrc[i];
            float l0 = g_asrc[sv * H] + ad0; l0 = l0 > 0.f ? l0 : 0.2f * l0;
            w0 = __expf(l0 - m0); sm0 += w0;
            if (H == 2) {
                float l1 = g_asrc[sv * H + 1] + ad1; l1 = l1 > 0.f ? l1 : 0.2f * l1;
                w1 = __expf(l1 - m1); sm1 += w1;
            }
        }
        int cnt = s1 - base; if (cnt > 32) cnt = 32;
        for (int t = 0; t < cnt; t++) {
            int   sb  = __shfl_sync(0xffffffffu, sv, t);
            float wb0 = __shfl_sync(0xffffffffu, w0, t);
            float wb1 = (H == 2) ? __shfl_sync(0xffffffffu, w1, t) : 0.f;
#pragma unroll
            for (int j = 0; j < PL; j++) {
                int c = lane + j * 32;
                if (HC >= 32 || c < HC) {
                    float wv = (H == 2) ? (c < C ? wb0 : wb1) : wb0;
                    acc[j] += hbuf[(size_t)sb * HC + c] * wv;
                }
            }
        }
    }
#pragma unroll
    for (int o = 16; o; o >>= 1) {
        sm0 += __shfl_xor_sync(0xffffffffu, sm0, o);
        if (H == 2) sm1 += __shfl_xor_sync(0xffffffffu, sm1, o);
    }
    const float inv0 = 1.f / (sm0 + 1e-16f);
    const float inv1 = (H == 2) ? 1.f / (sm1 + 1e-16f) : 0.f;

    // pass 3: alpha writeback (original edge order)
    for (int i = s0 + lane; i < s1; i += 32) {
        int s = g_csrc[i];
        int e = g_eid[i];
        if (e < 0 || e >= nedges) continue;
        float l0 = g_asrc[s * H] + ad0; l0 = l0 > 0.f ? l0 : 0.2f * l0;
        alpha_out[(size_t)e * H] = __expf(l0 - m0) * inv0;
        if (H == 2) {
            float l1 = g_asrc[s * H + 1] + ad1; l1 = l1 > 0.f ? l1 : 0.2f * l1;
            alpha_out[(size_t)e * H + 1] = __expf(l1 - m1) * inv1;
        }
    }

    // epilogue: normalize, bias, optional relu
#pragma unroll
    for (int j = 0; j < PL; j++) {
        int c = lane + j * 32;
        if (HC >= 32 || c < HC) {
            float invv = (H == 2) ? (c < C ? inv0 : inv1) : inv0;
            float v = acc[j] * invv + bias[c];
            if (RELU) v = fmaxf(v, 0.f);
            outbuf[(size_t)n * HC + c] = v;
        }
    }
}

// ---------------------------------------------------------------------------
// Global mean pooling + classifier
// ---------------------------------------------------------------------------
__global__ void k_pool_init(float* __restrict__ gemb) {
    int t = threadIdx.x;
    if (t < 256) gemb[t] = 0.f;
    if (t < 16) g_cnt[t] = 0.f;
}

__global__ void k_pool(const int* __restrict__ batch, const float* __restrict__ emb,
                       float* __restrict__ gemb, int nnodes) {
    __shared__ float sh[256];
    __shared__ float shc[16];
    for (int i = threadIdx.x; i < 256; i += blockDim.x) sh[i] = 0.f;
    if (threadIdx.x < 16) shc[threadIdx.x] = 0.f;
    __syncthreads();
    int n = blockIdx.x * blockDim.x + threadIdx.x;
    if (n < nnodes) {
        int g = load_idx(batch, (size_t)n);
        g = g < 0 ? 0 : (g > 15 ? 15 : g);
        atomicAdd(&shc[g], 1.f);
        const float* row = emb + (size_t)n * 16;
#pragma unroll
        for (int c = 0; c < 16; c++) atomicAdd(&sh[g * 16 + c], row[c]);
    }
    __syncthreads();
    for (int i = threadIdx.x; i < 256; i += blockDim.x)
        if (sh[i] != 0.f) atomicAdd(&gemb[i], sh[i]);
    if (threadIdx.x < 16 && shc[threadIdx.x] != 0.f)
        atomicAdd(&g_cnt[threadIdx.x], shc[threadIdx.x]);
}

__global__ void k_final(const float* __restrict__ Wl, const float* __restrict__ bl,
                        float* __restrict__ gemb, float* __restrict__ logits) {
    __shared__ float ge[256];
    int t = threadIdx.x;
    if (t < 256) {
        int g = t >> 4;
        float cnt = g_cnt[g]; if (cnt < 1.f) cnt = 1.f;
        float v = gemb[t] / cnt;
        gemb[t] = v;   // normalized g_emb output
        ge[t] = v;
    }
    __syncthreads();
    if (t < 32) {
        int g = t >> 1, j = t & 1;
        float s = bl[j];
#pragma unroll
        for (int c = 0; c < 16; c++) s += ge[g * 16 + c] * Wl[c * 2 + j];
        logits[t] = s;  // final logits
    }
}

// ---------------------------------------------------------------------------
// Orchestration
// ---------------------------------------------------------------------------
extern "C" void kernel_launch(void* const* d_in, const int* in_sizes, int n_in,
                              void* d_out, int out_size) {
    // ---- input mapping: detect insertion-order vs alphabetical metadata ----
    // insertion:   x, edge_index, batch, W1, as1, ad1, b1, W2, as2, ad2, b2,
    //              W3, as3, ad3, b3, Wl, bl
    // alphabetical:W1, W2, W3, Wl, ad1, ad2, ad3, as1, as2, as3, b1, b2, b3,
    //              batch, bl, edge_index, x
    int ix, iei, ib, iW1, ias1, iad1, ib1, iW2, ias2, iad2, ib2,
        iW3, ias3, iad3, ib3, iWl, ibl;
    if (in_sizes[0] > 1000000) {  // x is first => insertion order
        ix = 0; iei = 1; ib = 2;
        iW1 = 3;  ias1 = 4;  iad1 = 5;  ib1 = 6;
        iW2 = 7;  ias2 = 8;  iad2 = 9;  ib2 = 10;
        iW3 = 11; ias3 = 12; iad3 = 13; ib3 = 14;
        iWl = 15; ibl = 16;
    } else {                       // alphabetical order
        iW1 = 0; iW2 = 1; iW3 = 2; iWl = 3;
        iad1 = 4; iad2 = 5; iad3 = 6;
        ias1 = 7; ias2 = 8; ias3 = 9;
        ib1 = 10; ib2 = 11; ib3 = 12;
        ib = 13; ibl = 14; iei = 15; ix = 16;
    }

    const float* x     = (const float*)d_in[ix];
    const int*   ei    = (const int*)d_in[iei];     // raw 32-bit words (int32 or int64)
    const int*   batch = (const int*)d_in[ib];
    const float* W1 = (const float*)d_in[iW1];
    const float* as1 = (const float*)d_in[ias1];
    const float* ad1 = (const float*)d_in[iad1];
    const float* b1  = (const float*)d_in[ib1];
    const float* W2 = (const float*)d_in[iW2];
    const float* as2 = (const float*)d_in[ias2];
    const float* ad2 = (const float*)d_in[iad2];
    const float* b2  = (const float*)d_in[ib2];
    const float* W3 = (const float*)d_in[iW3];
    const float* as3 = (const float*)d_in[ias3];
    const float* ad3 = (const float*)d_in[iad3];
    const float* b3  = (const float*)d_in[ib3];
    const float* Wl = (const float*)d_in[iWl];
    const float* bl = (const float*)d_in[ibl];
    float* out = (float*)d_out;

    int N = in_sizes[ix] / 128;
    int E = in_sizes[iei] / 2;
    if (N > NMAX) N = NMAX;
    if (E > EMAX) E = EMAX;

    // ---- scratch symbol addresses ----
    void* tmp;
    cudaGetSymbolAddress(&tmp, g_h);      float* h      = (float*)tmp;
    cudaGetSymbolAddress(&tmp, g_feat);   float* feat   = (float*)tmp;
    cudaGetSymbolAddress(&tmp, g_embS);   float* embS   = (float*)tmp;
    cudaGetSymbolAddress(&tmp, g_alphaS); float* alphaS = (float*)tmp;
    cudaGetSymbolAddress(&tmp, g_gembS);  float* gembS  = (float*)tmp;

    // ---- output layout (fall back to scratch if out buffer is smaller) ----
    // expected: logits[16,2] | g_emb[16,16] | emb[N,16] | a1[E,2] | a2[E] | a3[E]
    size_t oGemb = 32;
    size_t oEmb  = oGemb + 256;
    size_t oA1   = oEmb + (size_t)N * 16;
    size_t oA2   = oA1 + (size_t)E * 2;
    size_t oA3   = oA2 + (size_t)E;
    size_t FULL  = oA3 + (size_t)E;
    size_t osz = (size_t)out_size;
    float* OUT_gemb = (osz >= oEmb)  ? out + oGemb : gembS;
    float* OUT_emb  = (osz >= oA1)   ? out + oEmb  : embS;
    float* OUT_a1   = (osz >= oA2)   ? out + oA1   : alphaS;
    float* OUT_a2   = (osz >= oA3)   ? out + oA2   : alphaS;
    float* OUT_a3   = (osz >= FULL)  ? out + oA3   : alphaS;

    const int TB = 256;
    const int gemmBlocks = (N + 63) / 64;
    const int warpBlocksN = (N + 7) / 8;           // 1 warp per node

    // ---- index width detection + CSR build (shared by all 3 layers) ----
    k_detect_width<<<1, 1>>>(ei);
    k_zero_deg<<<(N + TB - 1) / TB, TB>>>(N);
    k_hist<<<(E + TB - 1) / TB, TB>>>(ei, E, N);
    k_scan<<<1, 1024>>>(N);
    k_scatter<<<(E + TB - 1) / TB, TB>>>(ei, E, N);

    // ---- Layer 1: 128 -> (2 heads x 64), concat, +b1, relu ----
    k_gemm64<128><<<dim3(gemmBlocks, 2), TB>>>(x, W1, h, N);
    k_alpha<2, 64><<<(N * 2 + 7) / 8, TB>>>(h, as1, ad1, N);
    k_aggregate<2, 64, true><<<warpBlocksN, TB>>>(h, b1, feat, OUT_a1, N, E);

    // ---- Layer 2: 128 -> (1 head x 128), +b2, relu ----
    k_gemm64<128><<<dim3(gemmBlocks, 2), TB>>>(feat, W2, h, N);
    k_alpha<1, 128><<<(N + 7) / 8, TB>>>(h, as2, ad2, N);
    k_aggregate<1, 128, true><<<warpBlocksN, TB>>>(h, b2, feat, OUT_a2, N, E);

    // ---- Layer 3: 128 -> (1 head x 16), +b3 ----
    k_gemm16<<<((size_t)N * 16 + TB - 1) / TB, TB>>>(feat, W3, h, N);
    k_alpha<1, 16><<<(N + 7) / 8, TB>>>(h, as3, ad3, N);
    k_aggregate<1, 16, false><<<warpBlocksN, TB>>>(h, b3, OUT_emb, OUT_a3, N, E);

    // ---- Global mean pool + classifier ----
    k_pool_init<<<1, 256>>>(OUT_gemb);
    k_pool<<<(N + TB - 1) / TB, TB>>>(batch, OUT_emb, OUT_gemb, N);
    k_final<<<1, 256>>>(Wl, bl, OUT_gemb, out);
}

// round 8
// speedup vs baseline: 1.1502x; 1.1502x over previous
#include <cuda_runtime.h>
#include <cstdint>
#include <cstddef>

// ---------------------------------------------------------------------------
// Problem constants (match reference_code)
// ---------------------------------------------------------------------------
static constexpr int NMAX = 50000;    // nodes
static constexpr int EMAX = 850000;   // edges (800k random + 50k self loops)
static constexpr int NBMAX = 64;      // max scan blocks (ceil(50000/1024)=49)

// ---------------------------------------------------------------------------
// Scratch (static __device__ globals — no allocation allowed)
// ---------------------------------------------------------------------------
static __device__ __align__(16) float g_h[(size_t)NMAX * 128];     // pre-agg features
static __device__ __align__(16) float g_feat[(size_t)NMAX * 128];  // post-layer features
static __device__ float g_asrc[(size_t)NMAX * 2];
static __device__ float g_adst[(size_t)NMAX * 2];
static __device__ int   g_deg[NMAX];                 // histogram, then cursor
static __device__ int   g_rowstart[NMAX + 1];
static __device__ int   g_bsum[NBMAX];
static __device__ int   g_csrc[EMAX];                // src sorted by dst
static __device__ int   g_eid[EMAX];                 // original edge id
static __device__ float g_cnt[16];
static __device__ int   g_is64;                      // 1 if index buffers are int64
// fallback scratch if d_out is smaller than the full flattened tuple
static __device__ __align__(16) float g_embS[(size_t)NMAX * 16];
static __device__ __align__(16) float g_alphaS[(size_t)EMAX * 2];
static __device__ float g_gembS[256];

// ---------------------------------------------------------------------------
// Index width detection + decode (int32 vs int64 little-endian, values small)
// ---------------------------------------------------------------------------
__global__ void k_detect_width(const int* __restrict__ w) {
    int z = 0;
#pragma unroll
    for (int k = 0; k < 8; k++) z |= w[2 * k + 1];
    g_is64 = (z == 0) ? 1 : 0;
}

__device__ __forceinline__ int load_idx(const int* __restrict__ w, size_t i) {
    return g_is64 ? w[2 * i] : w[i];
}

// ---------------------------------------------------------------------------
// CSR build
// ---------------------------------------------------------------------------
__global__ void k_zero_deg(int n) {
    int i = blockIdx.x * blockDim.x + threadIdx.x;
    if (i < n) g_deg[i] = 0;
}

__global__ void k_hist(const int* __restrict__ ei, int E, int n) {
    int e = blockIdx.x * blockDim.x + threadIdx.x;
    if (e >= E) return;
    int d = load_idx(ei, (size_t)E + e);
    d = d < 0 ? 0 : (d >= n ? n - 1 : d);
    atomicAdd(&g_deg[d], 1);
}

// Hierarchical scan, stage 1: per-block exclusive scan; block sums to g_bsum.
// Also zeroes g_deg (reused as scatter cursor).
__global__ void k_scan_local(int n) {
    __shared__ int sh[1024];
    const int b = blockIdx.x, t = threadIdx.x;
    const int i = b * 1024 + t;
    int v = (i < n) ? g_deg[i] : 0;
    if (i < n) g_deg[i] = 0;
    sh[t] = v;
    __syncthreads();
    for (int off = 1; off < 1024; off <<= 1) {
        int tv = (t >= off) ? sh[t - off] : 0;
        __syncthreads();
        sh[t] += tv;
        __syncthreads();
    }
    if (i < n) g_rowstart[i] = sh[t] - v;   // exclusive, local to block
    if (t == 1023) g_bsum[b] = sh[1023];
}

// stage 2: exclusive scan of block sums (single tiny block); writes total.
__global__ void k_scan_bsum(int nb, int n) {
    __shared__ int sh[NBMAX];
    int t = threadIdx.x;
    int v = (t < nb) ? g_bsum[t] : 0;
    sh[t] = v;
    __syncthreads();
    for (int off = 1; off < NBMAX; off <<= 1) {
        int tv = (t >= off) ? sh[t - off] : 0;
        __syncthreads();
        sh[t] += tv;
        __syncthreads();
    }
    if (t < nb) g_bsum[t] = sh[t] - v;      // exclusive offset per block
    if (t == nb - 1) g_rowstart[n] = sh[t]; // inclusive total
}

// stage 3: add block offsets.
__global__ void k_scan_add(int n) {
    int i = blockIdx.x * 1024 + threadIdx.x;
    if (i < n) g_rowstart[i] += g_bsum[blockIdx.x];
}

__global__ void k_scatter(const int* __restrict__ ei, int E, int n) {
    int e = blockIdx.x * blockDim.x + threadIdx.x;
    if (e >= E) return;
    int d = load_idx(ei, (size_t)E + e);
    d = d < 0 ? 0 : (d >= n ? n - 1 : d);
    int s = load_idx(ei, (size_t)e);
    s = s < 0 ? 0 : (s >= n ? n - 1 : s);
    int pos = g_rowstart[d] + atomicAdd(&g_deg[d], 1);
    if (pos < EMAX) { g_csrc[pos] = s; g_eid[pos] = e; }
}

// ---------------------------------------------------------------------------
// GEMM: C[n, c] = sum_k A[n,k] * B[k,c], K = 128, COLS = 128
// BM=128, BN=128, BK=8, 256 threads, 8x8 micro-tile.
// Per k-step: 4 LDS.128 feed 64 FMA -> compute-limited, not LDS-limited.
// ---------------------------------------------------------------------------
__global__ __launch_bounds__(256) void k_gemm128(
        const float* __restrict__ A, const float* __restrict__ B,
        float* __restrict__ Cm, int nrows) {
    __shared__ float Ast[8][132];   // transposed A tile [k][m]
    __shared__ float Bs[8][132];
    const int tid = threadIdx.x;
    const int n0 = blockIdx.x * 128;
    const int ar = tid >> 1, akq = (tid & 1) << 2;   // A load: row, k-quad
    const int bk = tid >> 5, bq = (tid & 31) << 2;   // B load: k-row, col-quad
    const int tx = tid & 15, ty = tid >> 4;          // micro-tile coords
    const int gr = n0 + ar;

    float acc[8][8];
#pragma unroll
    for (int i = 0; i < 8; i++)
#pragma unroll
        for (int j = 0; j < 8; j++) acc[i][j] = 0.f;

    for (int kt = 0; kt < 128; kt += 8) {
        float4 av = make_float4(0.f, 0.f, 0.f, 0.f);
        if (gr < nrows) av = *(const float4*)(A + (size_t)gr * 128 + kt + akq);
        float4 bv = *(const float4*)(B + (size_t)(kt + bk) * 128 + bq);
        __syncthreads();
        Ast[akq + 0][ar] = av.x;
        Ast[akq + 1][ar] = av.y;
        Ast[akq + 2][ar] = av.z;
        Ast[akq + 3][ar] = av.w;
        *(float4*)(&Bs[bk][bq]) = bv;
        __syncthreads();
#pragma unroll
        for (int k = 0; k < 8; k++) {
            float4 a0 = *(const float4*)(&Ast[k][ty << 3]);
            float4 a1 = *(const float4*)(&Ast[k][(ty << 3) + 4]);
            float4 b0 = *(const float4*)(&Bs[k][tx << 3]);
            float4 b1 = *(const float4*)(&Bs[k][(tx << 3) + 4]);
            float am[8] = {a0.x, a0.y, a0.z, a0.w, a1.x, a1.y, a1.z, a1.w};
            float bn[8] = {b0.x, b0.y, b0.z, b0.w, b1.x, b1.y, b1.z, b1.w};
#pragma unroll
            for (int i = 0; i < 8; i++)
#pragma unroll
                for (int j = 0; j < 8; j++) acc[i][j] += am[i] * bn[j];
        }
    }
#pragma unroll
    for (int i = 0; i < 8; i++) {
        int row = n0 + (ty << 3) + i;
        if (row < nrows) {
            float4 v0 = {acc[i][0], acc[i][1], acc[i][2], acc[i][3]};
            float4 v1 = {acc[i][4], acc[i][5], acc[i][6], acc[i][7]};
            *(float4*)(Cm + (size_t)row * 128 + (tx << 3))     = v0;
            *(float4*)(Cm + (size_t)row * 128 + (tx << 3) + 4) = v1;
        }
    }
}

// Small GEMM for layer 3: [N,128] @ [128,16]
__global__ void k_gemm16(const float* __restrict__ A, const float* __restrict__ B,
                         float* __restrict__ Cm, int nrows) {
    __shared__ float Bs[128 * 16];
    for (int i = threadIdx.x; i < 128 * 16; i += blockDim.x) Bs[i] = B[i];
    __syncthreads();
    int idx = blockIdx.x * blockDim.x + threadIdx.x;
    int n = idx >> 4, c = idx & 15;
    if (n >= nrows) return;
    const float* a = A + (size_t)n * 128;
    float s = 0.f;
#pragma unroll
    for (int k = 0; k < 128; k++) s += a[k] * Bs[k * 16 + c];
    Cm[(size_t)n * 16 + c] = s;
}

// ---------------------------------------------------------------------------
// alpha_src / alpha_dst: one warp per (node, head)
// ---------------------------------------------------------------------------
template <int H, int C>
__global__ void k_alpha(const float* __restrict__ hbuf, const float* __restrict__ avs,
                        const float* __restrict__ avd, int nnodes) {
    int warp = (blockIdx.x * blockDim.x + threadIdx.x) >> 5;
    int lane = threadIdx.x & 31;
    if (warp >= nnodes * H) return;
    int hh = warp % H;
    const float* row = hbuf + (size_t)warp * C;
    float ss = 0.f, sd = 0.f;
    for (int c = lane; c < C; c += 32) {
        float v = row[c];
        ss += v * avs[hh * C + c];
        sd += v * avd[hh * C + c];
    }
#pragma unroll
    for (int o = 16; o; o >>= 1) {
        ss += __shfl_xor_sync(0xffffffffu, ss, o);
        sd += __shfl_xor_sync(0xffffffffu, sd, o);
    }
    if (lane == 0) { g_asrc[warp] = ss; g_adst[warp] = sd; }
}

// ---------------------------------------------------------------------------
// Fused per-node softmax + aggregation (gather over dst-CSR). One warp/node.
// float4 vectorized message accumulation: lane owns columns lane*4..lane*4+3.
// ---------------------------------------------------------------------------
template <int H, int C, bool RELU>
__global__ void k_aggregate(const float* __restrict__ hbuf, const float* __restrict__ bias,
                            float* __restrict__ outbuf, float* __restrict__ alpha_out,
                            int nnodes, int nedges) {
    constexpr int HC = H * C;
    constexpr int V4 = (HC + 127) / 128;   // float4 chunks per lane
    const int warp = (blockIdx.x * blockDim.x + threadIdx.x) >> 5;
    const int lane = threadIdx.x & 31;
    if (warp >= nnodes) return;
    const int n = warp;
    const int s0 = g_rowstart[n];
    const int s1 = g_rowstart[n + 1];

    const float ad0 = g_adst[n * H];
    const float ad1 = (H == 2) ? g_adst[n * H + 1] : 0.f;

    // pass 1: segment max of leaky logits
    float m0 = -1e30f, m1 = -1e30f;
    for (int i = s0 + lane; i < s1; i += 32) {
        int s = g_csrc[i];
        float l0 = g_asrc[s * H] + ad0; l0 = l0 > 0.f ? l0 : 0.2f * l0;
        m0 = fmaxf(m0, l0);
        if (H == 2) {
            float l1 = g_asrc[s * H + 1] + ad1; l1 = l1 > 0.f ? l1 : 0.2f * l1;
            m1 = fmaxf(m1, l1);
        }
    }
#pragma unroll
    for (int o = 16; o; o >>= 1) {
        m0 = fmaxf(m0, __shfl_xor_sync(0xffffffffu, m0, o));
        if (H == 2) m1 = fmaxf(m1, __shfl_xor_sync(0xffffffffu, m1, o));
    }

    // pass 2: sum of exps + unnormalized message accumulation (float4)
    float sm0 = 0.f, sm1 = 0.f;
    float4 acc[V4];
#pragma unroll
    for (int j = 0; j < V4; j++) acc[j] = make_float4(0.f, 0.f, 0.f, 0.f);

    // per-lane head weight selector: columns lane*4.. are in head (lane*4)/C
    for (int base = s0; base < s1; base += 32) {
        int i = base + lane;
        int sv = 0; float w0 = 0.f, w1 = 0.f;
        if (i < s1) {
            sv = g_csrc[i];
            float l0 = g_asrc[sv * H] + ad0; l0 = l0 > 0.f ? l0 : 0.2f * l0;
            w0 = __expf(l0 - m0); sm0 += w0;
            if (H == 2) {
                float l1 = g_asrc[sv * H + 1] + ad1; l1 = l1 > 0.f ? l1 : 0.2f * l1;
                w1 = __expf(l1 - m1); sm1 += w1;
            }
        }
        int cnt = s1 - base; if (cnt > 32) cnt = 32;
#pragma unroll 4
        for (int t = 0; t < cnt; t++) {
            int   sb  = __shfl_sync(0xffffffffu, sv, t);
            float wb0 = __shfl_sync(0xffffffffu, w0, t);
            float wb1 = (H == 2) ? __shfl_sync(0xffffffffu, w1, t) : 0.f;
            const float4* row4 = (const float4*)(hbuf + (size_t)sb * HC);
#pragma unroll
            for (int j = 0; j < V4; j++) {
                int c4 = lane + j * 32;           // float4 index; column = c4*4
                if (HC >= 128 || c4 * 4 < HC) {
                    float wv = (H == 2) ? ((c4 * 4) < C ? wb0 : wb1) : wb0;
                    float4 hv = row4[c4];
                    acc[j].x += hv.x * wv;
                    acc[j].y += hv.y * wv;
                    acc[j].z += hv.z * wv;
                    acc[j].w += hv.w * wv;
                }
            }
        }
    }
#pragma unroll
    for (int o = 16; o; o >>= 1) {
        sm0 += __shfl_xor_sync(0xffffffffu, sm0, o);
        if (H == 2) sm1 += __shfl_xor_sync(0xffffffffu, sm1, o);
    }
    const float inv0 = 1.f / (sm0 + 1e-16f);
    const float inv1 = (H == 2) ? 1.f / (sm1 + 1e-16f) : 0.f;

    // pass 3: alpha writeback (original edge order)
    for (int i = s0 + lane; i < s1; i += 32) {
        int s = g_csrc[i];
        int e = g_eid[i];
        if (e < 0 || e >= nedges) continue;
        float l0 = g_asrc[s * H] + ad0; l0 = l0 > 0.f ? l0 : 0.2f * l0;
        alpha_out[(size_t)e * H] = __expf(l0 - m0) * inv0;
        if (H == 2) {
            float l1 = g_asrc[s * H + 1] + ad1; l1 = l1 > 0.f ? l1 : 0.2f * l1;
            alpha_out[(size_t)e * H + 1] = __expf(l1 - m1) * inv1;
        }
    }

    // epilogue: normalize, bias, optional relu
#pragma unroll
    for (int j = 0; j < V4; j++) {
        int c4 = lane + j * 32;
        int c = c4 * 4;
        if (HC >= 128 || c < HC) {
            float invv = (H == 2) ? (c < C ? inv0 : inv1) : inv0;
            float4 v;
            v.x = acc[j].x * invv + bias[c + 0];
            v.y = acc[j].y * invv + bias[c + 1];
            v.z = acc[j].z * invv + bias[c + 2];
            v.w = acc[j].w * invv + bias[c + 3];
            if (RELU) {
                v.x = fmaxf(v.x, 0.f); v.y = fmaxf(v.y, 0.f);
                v.z = fmaxf(v.z, 0.f); v.w = fmaxf(v.w, 0.f);
            }
            *(float4*)(outbuf + (size_t)n * HC + c) = v;
        }
    }
}

// ---------------------------------------------------------------------------
// Global mean pooling + classifier
// ---------------------------------------------------------------------------
__global__ void k_pool_init(float* __restrict__ gemb) {
    int t = threadIdx.x;
    if (t < 256) gemb[t] = 0.f;
    if (t < 16) g_cnt[t] = 0.f;
}

__global__ void k_pool(const int* __restrict__ batch, const float* __restrict__ emb,
                       float* __restrict__ gemb, int nnodes) {
    __shared__ float sh[256];
    __shared__ float shc[16];
    for (int i = threadIdx.x; i < 256; i += blockDim.x) sh[i] = 0.f;
    if (threadIdx.x < 16) shc[threadIdx.x] = 0.f;
    __syncthreads();
    int n = blockIdx.x * blockDim.x + threadIdx.x;
    if (n < nnodes) {
        int g = load_idx(batch, (size_t)n);
        g = g < 0 ? 0 : (g > 15 ? 15 : g);
        atomicAdd(&shc[g], 1.f);
        const float* row = emb + (size_t)n * 16;
#pragma unroll
        for (int c = 0; c < 16; c++) atomicAdd(&sh[g * 16 + c], row[c]);
    }
    __syncthreads();
    for (int i = threadIdx.x; i < 256; i += blockDim.x)
        if (sh[i] != 0.f) atomicAdd(&gemb[i], sh[i]);
    if (threadIdx.x < 16 && shc[threadIdx.x] != 0.f)
        atomicAdd(&g_cnt[threadIdx.x], shc[threadIdx.x]);
}

__global__ void k_final(const float* __restrict__ Wl, const float* __restrict__ bl,
                        float* __restrict__ gemb, float* __restrict__ logits) {
    __shared__ float ge[256];
    int t = threadIdx.x;
    if (t < 256) {
        int g = t >> 4;
        float cnt = g_cnt[g]; if (cnt < 1.f) cnt = 1.f;
        float v = gemb[t] / cnt;
        gemb[t] = v;   // normalized g_emb output
        ge[t] = v;
    }
    __syncthreads();
    if (t < 32) {
        int g = t >> 1, j = t & 1;
        float s = bl[j];
#pragma unroll
        for (int c = 0; c < 16; c++) s += ge[g * 16 + c] * Wl[c * 2 + j];
        logits[t] = s;  // final logits
    }
}

// ---------------------------------------------------------------------------
// Orchestration
// ---------------------------------------------------------------------------
extern "C" void kernel_launch(void* const* d_in, const int* in_sizes, int n_in,
                              void* d_out, int out_size) {
    int ix, iei, ib, iW1, ias1, iad1, ib1, iW2, ias2, iad2, ib2,
        iW3, ias3, iad3, ib3, iWl, ibl;
    if (in_sizes[0] > 1000000) {  // x first => insertion order
        ix = 0; iei = 1; ib = 2;
        iW1 = 3;  ias1 = 4;  iad1 = 5;  ib1 = 6;
        iW2 = 7;  ias2 = 8;  iad2 = 9;  ib2 = 10;
        iW3 = 11; ias3 = 12; iad3 = 13; ib3 = 14;
        iWl = 15; ibl = 16;
    } else {                       // alphabetical order
        iW1 = 0; iW2 = 1; iW3 = 2; iWl = 3;
        iad1 = 4; iad2 = 5; iad3 = 6;
        ias1 = 7; ias2 = 8; ias3 = 9;
        ib1 = 10; ib2 = 11; ib3 = 12;
        ib = 13; ibl = 14; iei = 15; ix = 16;
    }

    const float* x     = (const float*)d_in[ix];
    const int*   ei    = (const int*)d_in[iei];
    const int*   batch = (const int*)d_in[ib];
    const float* W1 = (const float*)d_in[iW1];
    const float* as1 = (const float*)d_in[ias1];
    const float* ad1 = (const float*)d_in[iad1];
    const float* b1  = (const float*)d_in[ib1];
    const float* W2 = (const float*)d_in[iW2];
    const float* as2 = (const float*)d_in[ias2];
    const float* ad2 = (const float*)d_in[iad2];
    const float* b2  = (const float*)d_in[ib2];
    const float* W3 = (const float*)d_in[iW3];
    const float* as3 = (const float*)d_in[ias3];
    const float* ad3 = (const float*)d_in[iad3];
    const float* b3  = (const float*)d_in[ib3];
    const float* Wl = (const float*)d_in[iWl];
    const float* bl = (const float*)d_in[ibl];
    float* out = (float*)d_out;

    int N = in_sizes[ix] / 128;
    int E = in_sizes[iei] / 2;
    if (N > NMAX) N = NMAX;
    if (E > EMAX) E = EMAX;

    void* tmp;
    cudaGetSymbolAddress(&tmp, g_h);      float* h      = (float*)tmp;
    cudaGetSymbolAddress(&tmp, g_feat);   float* feat   = (float*)tmp;
    cudaGetSymbolAddress(&tmp, g_embS);   float* embS   = (float*)tmp;
    cudaGetSymbolAddress(&tmp, g_alphaS); float* alphaS = (float*)tmp;
    cudaGetSymbolAddress(&tmp, g_gembS);  float* gembS  = (float*)tmp;

    // output layout: logits[16,2] | g_emb[16,16] | emb[N,16] | a1[E,2] | a2[E] | a3[E]
    size_t oGemb = 32;
    size_t oEmb  = oGemb + 256;
    size_t oA1   = oEmb + (size_t)N * 16;
    size_t oA2   = oA1 + (size_t)E * 2;
    size_t oA3   = oA2 + (size_t)E;
    size_t FULL  = oA3 + (size_t)E;
    size_t osz = (size_t)out_size;
    float* OUT_gemb = (osz >= oEmb)  ? out + oGemb : gembS;
    float* OUT_emb  = (osz >= oA1)   ? out + oEmb  : embS;
    float* OUT_a1   = (osz >= oA2)   ? out + oA1   : alphaS;
    float* OUT_a2   = (osz >= oA3)   ? out + oA2   : alphaS;
    float* OUT_a3   = (osz >= FULL)  ? out + oA3   : alphaS;

    const int TB = 256;
    const int nb = (N + 1023) / 1024;              // scan blocks
    const int gemmBlocks = (N + 127) / 128;
    const int warpBlocksN = (N + 7) / 8;           // 1 warp per node

    // ---- index width detection + CSR build (shared by all 3 layers) ----
    k_detect_width<<<1, 1>>>(ei);
    k_zero_deg<<<(N + TB - 1) / TB, TB>>>(N);
    k_hist<<<(E + TB - 1) / TB, TB>>>(ei, E, N);
    k_scan_local<<<nb, 1024>>>(N);
    k_scan_bsum<<<1, NBMAX>>>(nb, N);
    k_scan_add<<<nb, 1024>>>(N);
    k_scatter<<<(E + TB - 1) / TB, TB>>>(ei, E, N);

    // ---- Layer 1: 128 -> (2 heads x 64), concat, +b1, relu ----
    k_gemm128<<<gemmBlocks, TB>>>(x, W1, h, N);
    k_alpha<2, 64><<<(N * 2 + 7) / 8, TB>>>(h, as1, ad1, N);
    k_aggregate<2, 64, true><<<warpBlocksN, TB>>>(h, b1, feat, OUT_a1, N, E);

    // ---- Layer 2: 128 -> (1 head x 128), +b2, relu ----
    k_gemm128<<<gemmBlocks, TB>>>(feat, W2, h, N);
    k_alpha<1, 128><<<(N + 7) / 8, TB>>>(h, as2, ad2, N);
    k_aggregate<1, 128, true><<<warpBlocksN, TB>>>(h, b2, feat, OUT_a2, N, E);

    // ---- Layer 3: 128 -> (1 head x 16), +b3 ----
    k_gemm16<<<((size_t)N * 16 + TB - 1) / TB, TB>>>(feat, W3, h, N);
    k_alpha<1, 16><<<(N + 7) / 8, TB>>>(h, as3, ad3, N);
    k_aggregate<1, 16, false><<<warpBlocksN, TB>>>(h, b3, OUT_emb, OUT_a3, N, E);

    // ---- Global mean pool + classifier ----
    k_pool_init<<<1, 256>>>(OUT_gemb);
    k_pool<<<(N + TB - 1) / TB, TB>>>(batch, OUT_emb, OUT_gemb, N);
    k_final<<<1, 256>>>(Wl, bl, OUT_gemb, out);
}

// round 9
// speedup vs baseline: 1.1670x; 1.0146x over previous
#include <cuda_runtime.h>
#include <cstdint>
#include <cstddef>

// ---------------------------------------------------------------------------
// Problem constants (match reference_code)
// ---------------------------------------------------------------------------
static constexpr int NMAX = 50000;    // nodes
static constexpr int EMAX = 850000;   // edges (800k random + 50k self loops)
static constexpr int NBMAX = 64;      // max scan blocks (ceil(50000/1024)=49)

// ---------------------------------------------------------------------------
// Scratch (static __device__ globals — no allocation allowed)
// ---------------------------------------------------------------------------
static __device__ __align__(16) float g_h[(size_t)NMAX * 128];     // pre-agg features
static __device__ __align__(16) float g_feat[(size_t)NMAX * 128];  // post-layer features
static __device__ float g_asrc[(size_t)NMAX * 2];
static __device__ float g_adst[(size_t)NMAX * 2];
static __device__ int   g_deg[NMAX];                 // histogram, then cursor
static __device__ int   g_rowstart[NMAX + 1];
static __device__ int   g_bsum[NBMAX];
static __device__ int   g_csrc[EMAX];                // src sorted by dst
static __device__ int   g_eid[EMAX];                 // original edge id
static __device__ float g_cnt[16];
static __device__ int   g_is64;                      // 1 if index buffers are int64
// fallback scratch if d_out is smaller than the full flattened tuple
static __device__ __align__(16) float g_embS[(size_t)NMAX * 16];
static __device__ __align__(16) float g_alphaS[(size_t)EMAX * 2];
static __device__ float g_gembS[256];

// ---------------------------------------------------------------------------
// Index width detection + decode (int32 vs int64 little-endian, values small)
// ---------------------------------------------------------------------------
__global__ void k_detect_width(const int* __restrict__ w) {
    int z = 0;
#pragma unroll
    for (int k = 0; k < 8; k++) z |= w[2 * k + 1];
    g_is64 = (z == 0) ? 1 : 0;
}

__device__ __forceinline__ int load_idx(const int* __restrict__ w, size_t i) {
    return g_is64 ? w[2 * i] : w[i];
}

// ---------------------------------------------------------------------------
// CSR build
// ---------------------------------------------------------------------------
__global__ void k_zero_deg(int n) {
    int i = blockIdx.x * blockDim.x + threadIdx.x;
    if (i < n) g_deg[i] = 0;
}

__global__ void k_hist(const int* __restrict__ ei, int E, int n) {
    int e = blockIdx.x * blockDim.x + threadIdx.x;
    if (e >= E) return;
    int d = load_idx(ei, (size_t)E + e);
    d = d < 0 ? 0 : (d >= n ? n - 1 : d);
    atomicAdd(&g_deg[d], 1);
}

// Hierarchical scan, stage 1: per-block exclusive scan; block sums to g_bsum.
__global__ void k_scan_local(int n) {
    __shared__ int sh[1024];
    const int b = blockIdx.x, t = threadIdx.x;
    const int i = b * 1024 + t;
    int v = (i < n) ? g_deg[i] : 0;
    if (i < n) g_deg[i] = 0;
    sh[t] = v;
    __syncthreads();
    for (int off = 1; off < 1024; off <<= 1) {
        int tv = (t >= off) ? sh[t - off] : 0;
        __syncthreads();
        sh[t] += tv;
        __syncthreads();
    }
    if (i < n) g_rowstart[i] = sh[t] - v;   // exclusive, local to block
    if (t == 1023) g_bsum[b] = sh[1023];
}

// stage 2: exclusive scan of block sums (single tiny block); writes total.
__global__ void k_scan_bsum(int nb, int n) {
    __shared__ int sh[NBMAX];
    int t = threadIdx.x;
    int v = (t < nb) ? g_bsum[t] : 0;
    sh[t] = v;
    __syncthreads();
    for (int off = 1; off < NBMAX; off <<= 1) {
        int tv = (t >= off) ? sh[t - off] : 0;
        __syncthreads();
        sh[t] += tv;
        __syncthreads();
    }
    if (t < nb) g_bsum[t] = sh[t] - v;      // exclusive offset per block
    if (t == nb - 1) g_rowstart[n] = sh[t]; // inclusive total
}

// stage 3: add block offsets.
__global__ void k_scan_add(int n) {
    int i = blockIdx.x * 1024 + threadIdx.x;
    if (i < n) g_rowstart[i] += g_bsum[blockIdx.x];
}

__global__ void k_scatter(const int* __restrict__ ei, int E, int n) {
    int e = blockIdx.x * blockDim.x + threadIdx.x;
    if (e >= E) return;
    int d = load_idx(ei, (size_t)E + e);
    d = d < 0 ? 0 : (d >= n ? n - 1 : d);
    int s = load_idx(ei, (size_t)e);
    s = s < 0 ? 0 : (s >= n ? n - 1 : s);
    int pos = g_rowstart[d] + atomicAdd(&g_deg[d], 1);
    if (pos < EMAX) { g_csrc[pos] = s; g_eid[pos] = e; }
}

// ---------------------------------------------------------------------------
// GEMM + fused alpha epilogue.
// C[n,c] = sum_k A[n,k]*B[k,c], K=COLS=128. BM=BN=128, BK=8, 256 thr, 8x8 tile.
// Double-buffered smem (1 sync per k-step). Epilogue computes
// alpha_src/alpha_dst row dots and writes g_asrc/g_adst directly.
// ---------------------------------------------------------------------------
template <int H>
__global__ __launch_bounds__(256) void k_gemm128(
        const float* __restrict__ A, const float* __restrict__ B,
        const float* __restrict__ avs, const float* __restrict__ avd,
        float* __restrict__ Cm, int nrows) {
    __shared__ float Ast[2][8][132];   // transposed A tile [buf][k][m]
    __shared__ float Bs[2][8][132];
    const int tid = threadIdx.x;
    const int n0 = blockIdx.x * 128;
    const int ar = tid >> 1, akq = (tid & 1) << 2;   // A load: row, k-quad
    const int bk = tid >> 5, bq = (tid & 31) << 2;   // B load: k-row, col-quad
    const int tx = tid & 15, ty = tid >> 4;          // micro-tile coords
    const int gr = n0 + ar;

    float acc[8][8];
#pragma unroll
    for (int i = 0; i < 8; i++)
#pragma unroll
        for (int j = 0; j < 8; j++) acc[i][j] = 0.f;

    // prologue: stage 0
    {
        float4 av = make_float4(0.f, 0.f, 0.f, 0.f);
        if (gr < nrows) av = *(const float4*)(A + (size_t)gr * 128 + akq);
        float4 bv = *(const float4*)(B + (size_t)bk * 128 + bq);
        Ast[0][akq + 0][ar] = av.x;
        Ast[0][akq + 1][ar] = av.y;
        Ast[0][akq + 2][ar] = av.z;
        Ast[0][akq + 3][ar] = av.w;
        *(float4*)(&Bs[0][bk][bq]) = bv;
    }
    __syncthreads();

    for (int kt = 0; kt < 128; kt += 8) {
        const int cur = (kt >> 3) & 1;
        const bool more = (kt + 8) < 128;
        float4 av2 = make_float4(0.f, 0.f, 0.f, 0.f), bv2;
        if (more) {
            if (gr < nrows) av2 = *(const float4*)(A + (size_t)gr * 128 + kt + 8 + akq);
            bv2 = *(const float4*)(B + (size_t)(kt + 8 + bk) * 128 + bq);
        }
#pragma unroll
        for (int k = 0; k < 8; k++) {
            float4 a0 = *(const float4*)(&Ast[cur][k][ty << 3]);
            float4 a1 = *(const float4*)(&Ast[cur][k][(ty << 3) + 4]);
            float4 b0 = *(const float4*)(&Bs[cur][k][tx << 3]);
            float4 b1 = *(const float4*)(&Bs[cur][k][(tx << 3) + 4]);
            float am[8] = {a0.x, a0.y, a0.z, a0.w, a1.x, a1.y, a1.z, a1.w};
            float bn[8] = {b0.x, b0.y, b0.z, b0.w, b1.x, b1.y, b1.z, b1.w};
#pragma unroll
            for (int i = 0; i < 8; i++)
#pragma unroll
                for (int j = 0; j < 8; j++) acc[i][j] += am[i] * bn[j];
        }
        if (more) {
            const int nxt = cur ^ 1;
            Ast[nxt][akq + 0][ar] = av2.x;
            Ast[nxt][akq + 1][ar] = av2.y;
            Ast[nxt][akq + 2][ar] = av2.z;
            Ast[nxt][akq + 3][ar] = av2.w;
            *(float4*)(&Bs[nxt][bk][bq]) = bv2;
        }
        __syncthreads();
    }

    // fused alpha epilogue: per-thread column slice of a_src/a_dst (128-vec)
    float asv[8], adv[8];
    *(float4*)(asv)     = *(const float4*)(avs + (tx << 3));
    *(float4*)(asv + 4) = *(const float4*)(avs + (tx << 3) + 4);
    *(float4*)(adv)     = *(const float4*)(avd + (tx << 3));
    *(float4*)(adv + 4) = *(const float4*)(avd + (tx << 3) + 4);

#pragma unroll
    for (int i = 0; i < 8; i++) {
        const int row = n0 + (ty << 3) + i;
        float ps = 0.f, pd = 0.f;
#pragma unroll
        for (int j = 0; j < 8; j++) { ps += acc[i][j] * asv[j]; pd += acc[i][j] * adv[j]; }
        if (H == 1) {
#pragma unroll
            for (int o = 8; o; o >>= 1) {
                ps += __shfl_xor_sync(0xffffffffu, ps, o);
                pd += __shfl_xor_sync(0xffffffffu, pd, o);
            }
            if (tx == 0 && row < nrows) { g_asrc[row] = ps; g_adst[row] = pd; }
        } else {  // H == 2: tx 0..7 = head 0 cols, tx 8..15 = head 1 cols
#pragma unroll
            for (int o = 4; o; o >>= 1) {
                ps += __shfl_xor_sync(0xffffffffu, ps, o);
                pd += __shfl_xor_sync(0xffffffffu, pd, o);
            }
            if ((tx & 7) == 0 && row < nrows) {
                int hh = tx >> 3;
                g_asrc[row * 2 + hh] = ps;
                g_adst[row * 2 + hh] = pd;
            }
        }
        if (row < nrows) {
            float4 v0 = {acc[i][0], acc[i][1], acc[i][2], acc[i][3]};
            float4 v1 = {acc[i][4], acc[i][5], acc[i][6], acc[i][7]};
            *(float4*)(Cm + (size_t)row * 128 + (tx << 3))     = v0;
            *(float4*)(Cm + (size_t)row * 128 + (tx << 3) + 4) = v1;
        }
    }
}

// Small GEMM for layer 3 ([N,128] @ [128,16]) + fused alpha (H=1, C=16).
// 16 threads per row (one per output column). No early return: shfl-safe.
__global__ void k_gemm16(const float* __restrict__ A, const float* __restrict__ B,
                         const float* __restrict__ avs, const float* __restrict__ avd,
                         float* __restrict__ Cm, int nrows) {
    __shared__ float Bsm[128 * 16];
    for (int i = threadIdx.x; i < 128 * 16; i += blockDim.x) Bsm[i] = B[i];
    __syncthreads();
    int idx = blockIdx.x * blockDim.x + threadIdx.x;
    int n = idx >> 4, c = idx & 15;
    float s = 0.f;
    if (n < nrows) {
        const float* a = A + (size_t)n * 128;
#pragma unroll
        for (int k = 0; k < 128; k++) s += a[k] * Bsm[k * 16 + c];
    }
    // fused alpha: reduce s*avs[c] over the 16 lanes of this row
    float ps = s * avs[c];
    float pd = s * avd[c];
#pragma unroll
    for (int o = 8; o; o >>= 1) {
        ps += __shfl_xor_sync(0xffffffffu, ps, o);
        pd += __shfl_xor_sync(0xffffffffu, pd, o);
    }
    if (n < nrows) {
        Cm[(size_t)n * 16 + c] = s;
        if (c == 0) { g_asrc[n] = ps; g_adst[n] = pd; }
    }
}

// ---------------------------------------------------------------------------
// Fused per-node softmax + aggregation (gather over dst-CSR). One warp/node.
// float4 vectorized message accumulation: lane owns columns lane*4..lane*4+3.
// ---------------------------------------------------------------------------
template <int H, int C, bool RELU>
__global__ void k_aggregate(const float* __restrict__ hbuf, const float* __restrict__ bias,
                            float* __restrict__ outbuf, float* __restrict__ alpha_out,
                            int nnodes, int nedges) {
    constexpr int HC = H * C;
    constexpr int V4 = (HC + 127) / 128;   // float4 chunks per lane
    const int warp = (blockIdx.x * blockDim.x + threadIdx.x) >> 5;
    const int lane = threadIdx.x & 31;
    if (warp >= nnodes) return;
    const int n = warp;
    const int s0 = g_rowstart[n];
    const int s1 = g_rowstart[n + 1];

    const float ad0 = g_adst[n * H];
    const float ad1 = (H == 2) ? g_adst[n * H + 1] : 0.f;

    // pass 1: segment max of leaky logits
    float m0 = -1e30f, m1 = -1e30f;
    for (int i = s0 + lane; i < s1; i += 32) {
        int s = g_csrc[i];
        float l0 = g_asrc[s * H] + ad0; l0 = l0 > 0.f ? l0 : 0.2f * l0;
        m0 = fmaxf(m0, l0);
        if (H == 2) {
            float l1 = g_asrc[s * H + 1] + ad1; l1 = l1 > 0.f ? l1 : 0.2f * l1;
            m1 = fmaxf(m1, l1);
        }
    }
#pragma unroll
    for (int o = 16; o; o >>= 1) {
        m0 = fmaxf(m0, __shfl_xor_sync(0xffffffffu, m0, o));
        if (H == 2) m1 = fmaxf(m1, __shfl_xor_sync(0xffffffffu, m1, o));
    }

    // pass 2: sum of exps + unnormalized message accumulation (float4)
    float sm0 = 0.f, sm1 = 0.f;
    float4 acc[V4];
#pragma unroll
    for (int j = 0; j < V4; j++) acc[j] = make_float4(0.f, 0.f, 0.f, 0.f);

    for (int base = s0; base < s1; base += 32) {
        int i = base + lane;
        int sv = 0; float w0 = 0.f, w1 = 0.f;
        if (i < s1) {
            sv = g_csrc[i];
            float l0 = g_asrc[sv * H] + ad0; l0 = l0 > 0.f ? l0 : 0.2f * l0;
            w0 = __expf(l0 - m0); sm0 += w0;
            if (H == 2) {
                float l1 = g_asrc[sv * H + 1] + ad1; l1 = l1 > 0.f ? l1 : 0.2f * l1;
                w1 = __expf(l1 - m1); sm1 += w1;
            }
        }
        int cnt = s1 - base; if (cnt > 32) cnt = 32;
#pragma unroll 4
        for (int t = 0; t < cnt; t++) {
            int   sb  = __shfl_sync(0xffffffffu, sv, t);
            float wb0 = __shfl_sync(0xffffffffu, w0, t);
            float wb1 = (H == 2) ? __shfl_sync(0xffffffffu, w1, t) : 0.f;
            const float4* row4 = (const float4*)(hbuf + (size_t)sb * HC);
#pragma unroll
            for (int j = 0; j < V4; j++) {
                int c4 = lane + j * 32;           // float4 index; column = c4*4
                if (HC >= 128 || c4 * 4 < HC) {
                    float wv = (H == 2) ? ((c4 * 4) < C ? wb0 : wb1) : wb0;
                    float4 hv = row4[c4];
                    acc[j].x += hv.x * wv;
                    acc[j].y += hv.y * wv;
                    acc[j].z += hv.z * wv;
                    acc[j].w += hv.w * wv;
                }
            }
        }
    }
#pragma unroll
    for (int o = 16; o; o >>= 1) {
        sm0 += __shfl_xor_sync(0xffffffffu, sm0, o);
        if (H == 2) sm1 += __shfl_xor_sync(0xffffffffu, sm1, o);
    }
    const float inv0 = 1.f / (sm0 + 1e-16f);
    const float inv1 = (H == 2) ? 1.f / (sm1 + 1e-16f) : 0.f;

    // pass 3: alpha writeback (original edge order)
    for (int i = s0 + lane; i < s1; i += 32) {
        int s = g_csrc[i];
        int e = g_eid[i];
        if (e < 0 || e >= nedges) continue;
        float l0 = g_asrc[s * H] + ad0; l0 = l0 > 0.f ? l0 : 0.2f * l0;
        alpha_out[(size_t)e * H] = __expf(l0 - m0) * inv0;
        if (H == 2) {
            float l1 = g_asrc[s * H + 1] + ad1; l1 = l1 > 0.f ? l1 : 0.2f * l1;
            alpha_out[(size_t)e * H + 1] = __expf(l1 - m1) * inv1;
        }
    }

    // epilogue: normalize, bias, optional relu
#pragma unroll
    for (int j = 0; j < V4; j++) {
        int c4 = lane + j * 32;
        int c = c4 * 4;
        if (HC >= 128 || c < HC) {
            float invv = (H == 2) ? (c < C ? inv0 : inv1) : inv0;
            float4 v;
            v.x = acc[j].x * invv + bias[c + 0];
            v.y = acc[j].y * invv + bias[c + 1];
            v.z = acc[j].z * invv + bias[c + 2];
            v.w = acc[j].w * invv + bias[c + 3];
            if (RELU) {
                v.x = fmaxf(v.x, 0.f); v.y = fmaxf(v.y, 0.f);
                v.z = fmaxf(v.z, 0.f); v.w = fmaxf(v.w, 0.f);
            }
            *(float4*)(outbuf + (size_t)n * HC + c) = v;
        }
    }
}

// ---------------------------------------------------------------------------
// Global mean pooling + classifier
// ---------------------------------------------------------------------------
__global__ void k_pool_init(float* __restrict__ gemb) {
    int t = threadIdx.x;
    if (t < 256) gemb[t] = 0.f;
    if (t < 16) g_cnt[t] = 0.f;
}

__global__ void k_pool(const int* __restrict__ batch, const float* __restrict__ emb,
                       float* __restrict__ gemb, int nnodes) {
    __shared__ float sh[256];
    __shared__ float shc[16];
    for (int i = threadIdx.x; i < 256; i += blockDim.x) sh[i] = 0.f;
    if (threadIdx.x < 16) shc[threadIdx.x] = 0.f;
    __syncthreads();
    int n = blockIdx.x * blockDim.x + threadIdx.x;
    if (n < nnodes) {
        int g = load_idx(batch, (size_t)n);
        g = g < 0 ? 0 : (g > 15 ? 15 : g);
        atomicAdd(&shc[g], 1.f);
        const float* row = emb + (size_t)n * 16;
#pragma unroll
        for (int c = 0; c < 16; c++) atomicAdd(&sh[g * 16 + c], row[c]);
    }
    __syncthreads();
    for (int i = threadIdx.x; i < 256; i += blockDim.x)
        if (sh[i] != 0.f) atomicAdd(&gemb[i], sh[i]);
    if (threadIdx.x < 16 && shc[threadIdx.x] != 0.f)
        atomicAdd(&g_cnt[threadIdx.x], shc[threadIdx.x]);
}

__global__ void k_final(const float* __restrict__ Wl, const float* __restrict__ bl,
                        float* __restrict__ gemb, float* __restrict__ logits) {
    __shared__ float ge[256];
    int t = threadIdx.x;
    if (t < 256) {
        int g = t >> 4;
        float cnt = g_cnt[g]; if (cnt < 1.f) cnt = 1.f;
        float v = gemb[t] / cnt;
        gemb[t] = v;   // normalized g_emb output
        ge[t] = v;
    }
    __syncthreads();
    if (t < 32) {
        int g = t >> 1, j = t & 1;
        float s = bl[j];
#pragma unroll
        for (int c = 0; c < 16; c++) s += ge[g * 16 + c] * Wl[c * 2 + j];
        logits[t] = s;  // final logits
    }
}

// ---------------------------------------------------------------------------
// Orchestration
// ---------------------------------------------------------------------------
extern "C" void kernel_launch(void* const* d_in, const int* in_sizes, int n_in,
                              void* d_out, int out_size) {
    int ix, iei, ib, iW1, ias1, iad1, ib1, iW2, ias2, iad2, ib2,
        iW3, ias3, iad3, ib3, iWl, ibl;
    if (in_sizes[0] > 1000000) {  // x first => insertion order
        ix = 0; iei = 1; ib = 2;
        iW1 = 3;  ias1 = 4;  iad1 = 5;  ib1 = 6;
        iW2 = 7;  ias2 = 8;  iad2 = 9;  ib2 = 10;
        iW3 = 11; ias3 = 12; iad3 = 13; ib3 = 14;
        iWl = 15; ibl = 16;
    } else {                       // alphabetical order
        iW1 = 0; iW2 = 1; iW3 = 2; iWl = 3;
        iad1 = 4; iad2 = 5; iad3 = 6;
        ias1 = 7; ias2 = 8; ias3 = 9;
        ib1 = 10; ib2 = 11; ib3 = 12;
        ib = 13; ibl = 14; iei = 15; ix = 16;
    }

    const float* x     = (const float*)d_in[ix];
    const int*   ei    = (const int*)d_in[iei];
    const int*   batch = (const int*)d_in[ib];
    const float* W1 = (const float*)d_in[iW1];
    const float* as1 = (const float*)d_in[ias1];
    const float* ad1 = (const float*)d_in[iad1];
    const float* b1  = (const float*)d_in[ib1];
    const float* W2 = (const float*)d_in[iW2];
    const float* as2 = (const float*)d_in[ias2];
    const float* ad2 = (const float*)d_in[iad2];
    const float* b2  = (const float*)d_in[ib2];
    const float* W3 = (const float*)d_in[iW3];
    const float* as3 = (const float*)d_in[ias3];
    const float* ad3 = (const float*)d_in[iad3];
    const float* b3  = (const float*)d_in[ib3];
    const float* Wl = (const float*)d_in[iWl];
    const float* bl = (const float*)d_in[ibl];
    float* out = (float*)d_out;

    int N = in_sizes[ix] / 128;
    int E = in_sizes[iei] / 2;
    if (N > NMAX) N = NMAX;
    if (E > EMAX) E = EMAX;

    void* tmp;
    cudaGetSymbolAddress(&tmp, g_h);      float* h      = (float*)tmp;
    cudaGetSymbolAddress(&tmp, g_feat);   float* feat   = (float*)tmp;
    cudaGetSymbolAddress(&tmp, g_embS);   float* embS   = (float*)tmp;
    cudaGetSymbolAddress(&tmp, g_alphaS); float* alphaS = (float*)tmp;
    cudaGetSymbolAddress(&tmp, g_gembS);  float* gembS  = (float*)tmp;

    // output layout: logits[16,2] | g_emb[16,16] | emb[N,16] | a1[E,2] | a2[E] | a3[E]
    size_t oGemb = 32;
    size_t oEmb  = oGemb + 256;
    size_t oA1   = oEmb + (size_t)N * 16;
    size_t oA2   = oA1 + (size_t)E * 2;
    size_t oA3   = oA2 + (size_t)E;
    size_t FULL  = oA3 + (size_t)E;
    size_t osz = (size_t)out_size;
    float* OUT_gemb = (osz >= oEmb)  ? out + oGemb : gembS;
    float* OUT_emb  = (osz >= oA1)   ? out + oEmb  : embS;
    float* OUT_a1   = (osz >= oA2)   ? out + oA1   : alphaS;
    float* OUT_a2   = (osz >= oA3)   ? out + oA2   : alphaS;
    float* OUT_a3   = (osz >= FULL)  ? out + oA3   : alphaS;

    const int TB = 256;
    const int nb = (N + 1023) / 1024;              // scan blocks
    const int gemmBlocks = (N + 127) / 128;
    const int warpBlocksN = (N + 7) / 8;           // 1 warp per node

    // ---- index width detection + CSR build (shared by all 3 layers) ----
    k_detect_width<<<1, 1>>>(ei);
    k_zero_deg<<<(N + TB - 1) / TB, TB>>>(N);
    k_hist<<<(E + TB - 1) / TB, TB>>>(ei, E, N);
    k_scan_local<<<nb, 1024>>>(N);
    k_scan_bsum<<<1, NBMAX>>>(nb, N);
    k_scan_add<<<nb, 1024>>>(N);
    k_scatter<<<(E + TB - 1) / TB, TB>>>(ei, E, N);

    // ---- Layer 1: 128 -> (2 heads x 64), concat, +b1, relu ----
    k_gemm128<2><<<gemmBlocks, TB>>>(x, W1, as1, ad1, h, N);
    k_aggregate<2, 64, true><<<warpBlocksN, TB>>>(h, b1, feat, OUT_a1, N, E);

    // ---- Layer 2: 128 -> (1 head x 128), +b2, relu ----
    k_gemm128<1><<<gemmBlocks, TB>>>(feat, W2, as2, ad2, h, N);
    k_aggregate<1, 128, true><<<warpBlocksN, TB>>>(h, b2, feat, OUT_a2, N, E);

    // ---- Layer 3: 128 -> (1 head x 16), +b3 ----
    k_gemm16<<<((size_t)N * 16 + TB - 1) / TB, TB>>>(feat, W3, as3, ad3, h, N);
    k_aggregate<1, 16, false><<<warpBlocksN, TB>>>(h, b3, OUT_emb, OUT_a3, N, E);

    // ---- Global mean pool + classifier ----
    k_pool_init<<<1, 256>>>(OUT_gemb);
    k_pool<<<(N + TB - 1) / TB, TB>>>(batch, OUT_emb, OUT_gemb, N);
    k_final<<<1, 256>>>(Wl, bl, OUT_gemb, out);
}

// round 10
// speedup vs baseline: 1.2590x; 1.0788x over previous
#include <cuda_runtime.h>
#include <cstdint>
#include <cstddef>

// ---------------------------------------------------------------------------
// Problem constants (match reference_code)
// ---------------------------------------------------------------------------
static constexpr int NMAX = 50000;    // nodes
static constexpr int EMAX = 850000;   // edges (800k random + 50k self loops)
static constexpr int NBMAX = 64;      // max scan blocks (ceil(50000/1024)=49)

// ---------------------------------------------------------------------------
// Scratch (static __device__ globals — no allocation allowed)
// ---------------------------------------------------------------------------
static __device__ __align__(16) float g_h[(size_t)NMAX * 128];     // pre-agg features
static __device__ __align__(16) float g_feat[(size_t)NMAX * 128];  // post-layer features
static __device__ float g_asrc[(size_t)NMAX * 2];
static __device__ float g_adst[(size_t)NMAX * 2];
static __device__ int   g_deg[NMAX];                 // histogram, then cursor
static __device__ int   g_rowstart[NMAX + 1];
static __device__ int   g_bsum[NBMAX];
static __device__ int   g_csrc[EMAX];                // src sorted by dst
static __device__ int   g_eid[EMAX];                 // original edge id
static __device__ float g_cnt[16];
static __device__ int   g_is64;                      // 1 if index buffers are int64
// fallback scratch if d_out is smaller than the full flattened tuple
static __device__ __align__(16) float g_embS[(size_t)NMAX * 16];
static __device__ __align__(16) float g_alphaS[(size_t)EMAX * 2];
static __device__ float g_gembS[256];

// ---------------------------------------------------------------------------
// Index width detection + decode (int32 vs int64 little-endian, values small)
// ---------------------------------------------------------------------------
__global__ void k_detect_width(const int* __restrict__ w) {
    int z = 0;
#pragma unroll
    for (int k = 0; k < 8; k++) z |= w[2 * k + 1];
    g_is64 = (z == 0) ? 1 : 0;
}

__device__ __forceinline__ int load_idx(const int* __restrict__ w, size_t i) {
    return g_is64 ? w[2 * i] : w[i];
}

// ---------------------------------------------------------------------------
// CSR build
// ---------------------------------------------------------------------------
__global__ void k_zero_deg(int n) {
    int i = blockIdx.x * blockDim.x + threadIdx.x;
    if (i < n) g_deg[i] = 0;
}

__global__ void k_hist(const int* __restrict__ ei, int E, int n) {
    int e = blockIdx.x * blockDim.x + threadIdx.x;
    if (e >= E) return;
    int d = load_idx(ei, (size_t)E + e);
    d = d < 0 ? 0 : (d >= n ? n - 1 : d);
    atomicAdd(&g_deg[d], 1);
}

// Hierarchical scan, stage 1: per-block exclusive scan; block sums to g_bsum.
__global__ void k_scan_local(int n) {
    __shared__ int sh[1024];
    const int b = blockIdx.x, t = threadIdx.x;
    const int i = b * 1024 + t;
    int v = (i < n) ? g_deg[i] : 0;
    if (i < n) g_deg[i] = 0;
    sh[t] = v;
    __syncthreads();
    for (int off = 1; off < 1024; off <<= 1) {
        int tv = (t >= off) ? sh[t - off] : 0;
        __syncthreads();
        sh[t] += tv;
        __syncthreads();
    }
    if (i < n) g_rowstart[i] = sh[t] - v;   // exclusive, local to block
    if (t == 1023) g_bsum[b] = sh[1023];
}

// stage 2: exclusive scan of block sums (single tiny block); writes total.
__global__ void k_scan_bsum(int nb, int n) {
    __shared__ int sh[NBMAX];
    int t = threadIdx.x;
    int v = (t < nb) ? g_bsum[t] : 0;
    sh[t] = v;
    __syncthreads();
    for (int off = 1; off < NBMAX; off <<= 1) {
        int tv = (t >= off) ? sh[t - off] : 0;
        __syncthreads();
        sh[t] += tv;
        __syncthreads();
    }
    if (t < nb) g_bsum[t] = sh[t] - v;      // exclusive offset per block
    if (t == nb - 1) g_rowstart[n] = sh[t]; // inclusive total
}

// stage 3: add block offsets.
__global__ void k_scan_add(int n) {
    int i = blockIdx.x * 1024 + threadIdx.x;
    if (i < n) g_rowstart[i] += g_bsum[blockIdx.x];
}

__global__ void k_scatter(const int* __restrict__ ei, int E, int n) {
    int e = blockIdx.x * blockDim.x + threadIdx.x;
    if (e >= E) return;
    int d = load_idx(ei, (size_t)E + e);
    d = d < 0 ? 0 : (d >= n ? n - 1 : d);
    int s = load_idx(ei, (size_t)e);
    s = s < 0 ? 0 : (s >= n ? n - 1 : s);
    int pos = g_rowstart[d] + atomicAdd(&g_deg[d], 1);
    if (pos < EMAX) { g_csrc[pos] = s; g_eid[pos] = e; }
}

// ---------------------------------------------------------------------------
// GEMM + fused alpha epilogue.
// C[n,c] = sum_k A[n,k]*B[k,c], K=COLS=128. BM=BN=128, BK=8, 256 thr, 8x8 tile.
// Double-buffered smem (1 sync per k-step). Epilogue computes
// alpha_src/alpha_dst row dots and writes g_asrc/g_adst directly.
// ---------------------------------------------------------------------------
template <int H>
__global__ __launch_bounds__(256) void k_gemm128(
        const float* __restrict__ A, const float* __restrict__ B,
        const float* __restrict__ avs, const float* __restrict__ avd,
        float* __restrict__ Cm, int nrows) {
    __shared__ float Ast[2][8][132];   // transposed A tile [buf][k][m]
    __shared__ float Bs[2][8][132];
    const int tid = threadIdx.x;
    const int n0 = blockIdx.x * 128;
    const int ar = tid >> 1, akq = (tid & 1) << 2;   // A load: row, k-quad
    const int bk = tid >> 5, bq = (tid & 31) << 2;   // B load: k-row, col-quad
    const int tx = tid & 15, ty = tid >> 4;          // micro-tile coords
    const int gr = n0 + ar;

    float acc[8][8];
#pragma unroll
    for (int i = 0; i < 8; i++)
#pragma unroll
        for (int j = 0; j < 8; j++) acc[i][j] = 0.f;

    // prologue: stage 0
    {
        float4 av = make_float4(0.f, 0.f, 0.f, 0.f);
        if (gr < nrows) av = *(const float4*)(A + (size_t)gr * 128 + akq);
        float4 bv = *(const float4*)(B + (size_t)bk * 128 + bq);
        Ast[0][akq + 0][ar] = av.x;
        Ast[0][akq + 1][ar] = av.y;
        Ast[0][akq + 2][ar] = av.z;
        Ast[0][akq + 3][ar] = av.w;
        *(float4*)(&Bs[0][bk][bq]) = bv;
    }
    __syncthreads();

    for (int kt = 0; kt < 128; kt += 8) {
        const int cur = (kt >> 3) & 1;
        const bool more = (kt + 8) < 128;
        float4 av2 = make_float4(0.f, 0.f, 0.f, 0.f), bv2;
        if (more) {
            if (gr < nrows) av2 = *(const float4*)(A + (size_t)gr * 128 + kt + 8 + akq);
            bv2 = *(const float4*)(B + (size_t)(kt + 8 + bk) * 128 + bq);
        }
#pragma unroll
        for (int k = 0; k < 8; k++) {
            float4 a0 = *(const float4*)(&Ast[cur][k][ty << 3]);
            float4 a1 = *(const float4*)(&Ast[cur][k][(ty << 3) + 4]);
            float4 b0 = *(const float4*)(&Bs[cur][k][tx << 3]);
            float4 b1 = *(const float4*)(&Bs[cur][k][(tx << 3) + 4]);
            float am[8] = {a0.x, a0.y, a0.z, a0.w, a1.x, a1.y, a1.z, a1.w};
            float bn[8] = {b0.x, b0.y, b0.z, b0.w, b1.x, b1.y, b1.z, b1.w};
#pragma unroll
            for (int i = 0; i < 8; i++)
#pragma unroll
                for (int j = 0; j < 8; j++) acc[i][j] += am[i] * bn[j];
        }
        if (more) {
            const int nxt = cur ^ 1;
            Ast[nxt][akq + 0][ar] = av2.x;
            Ast[nxt][akq + 1][ar] = av2.y;
            Ast[nxt][akq + 2][ar] = av2.z;
            Ast[nxt][akq + 3][ar] = av2.w;
            *(float4*)(&Bs[nxt][bk][bq]) = bv2;
        }
        __syncthreads();
    }

    // fused alpha epilogue: per-thread column slice of a_src/a_dst (128-vec)
    float asv[8], adv[8];
    *(float4*)(asv)     = *(const float4*)(avs + (tx << 3));
    *(float4*)(asv + 4) = *(const float4*)(avs + (tx << 3) + 4);
    *(float4*)(adv)     = *(const float4*)(avd + (tx << 3));
    *(float4*)(adv + 4) = *(const float4*)(avd + (tx << 3) + 4);

#pragma unroll
    for (int i = 0; i < 8; i++) {
        const int row = n0 + (ty << 3) + i;
        float ps = 0.f, pd = 0.f;
#pragma unroll
        for (int j = 0; j < 8; j++) { ps += acc[i][j] * asv[j]; pd += acc[i][j] * adv[j]; }
        if (H == 1) {
#pragma unroll
            for (int o = 8; o; o >>= 1) {
                ps += __shfl_xor_sync(0xffffffffu, ps, o);
                pd += __shfl_xor_sync(0xffffffffu, pd, o);
            }
            if (tx == 0 && row < nrows) { g_asrc[row] = ps; g_adst[row] = pd; }
        } else {  // H == 2: tx 0..7 = head 0 cols, tx 8..15 = head 1 cols
#pragma unroll
            for (int o = 4; o; o >>= 1) {
                ps += __shfl_xor_sync(0xffffffffu, ps, o);
                pd += __shfl_xor_sync(0xffffffffu, pd, o);
            }
            if ((tx & 7) == 0 && row < nrows) {
                int hh = tx >> 3;
                g_asrc[row * 2 + hh] = ps;
                g_adst[row * 2 + hh] = pd;
            }
        }
        if (row < nrows) {
            float4 v0 = {acc[i][0], acc[i][1], acc[i][2], acc[i][3]};
            float4 v1 = {acc[i][4], acc[i][5], acc[i][6], acc[i][7]};
            *(float4*)(Cm + (size_t)row * 128 + (tx << 3))     = v0;
            *(float4*)(Cm + (size_t)row * 128 + (tx << 3) + 4) = v1;
        }
    }
}

// Small GEMM for layer 3 ([N,128] @ [128,16]) + fused alpha (H=1, C=16).
__global__ void k_gemm16(const float* __restrict__ A, const float* __restrict__ B,
                         const float* __restrict__ avs, const float* __restrict__ avd,
                         float* __restrict__ Cm, int nrows) {
    __shared__ float Bsm[128 * 16];
    for (int i = threadIdx.x; i < 128 * 16; i += blockDim.x) Bsm[i] = B[i];
    __syncthreads();
    int idx = blockIdx.x * blockDim.x + threadIdx.x;
    int n = idx >> 4, c = idx & 15;
    float s = 0.f;
    if (n < nrows) {
        const float* a = A + (size_t)n * 128;
#pragma unroll
        for (int k = 0; k < 128; k++) s += a[k] * Bsm[k * 16 + c];
    }
    float ps = s * avs[c];
    float pd = s * avd[c];
#pragma unroll
    for (int o = 8; o; o >>= 1) {
        ps += __shfl_xor_sync(0xffffffffu, ps, o);
        pd += __shfl_xor_sync(0xffffffffu, pd, o);
    }
    if (n < nrows) {
        Cm[(size_t)n * 16 + c] = s;
        if (c == 0) { g_asrc[n] = ps; g_adst[n] = pd; }
    }
}

// ---------------------------------------------------------------------------
// Fused per-node softmax + aggregation (gather over dst-CSR). One warp/node.
// ---------------------------------------------------------------------------
template <int H, int C, bool RELU>
__global__ void k_aggregate(const float* __restrict__ hbuf, const float* __restrict__ bias,
                            float* __restrict__ outbuf, float* __restrict__ alpha_out,
                            int nnodes, int nedges) {
    constexpr int HC = H * C;
    constexpr int V4 = (HC + 127) / 128;   // float4 chunks per lane
    const int warp = (blockIdx.x * blockDim.x + threadIdx.x) >> 5;
    const int lane = threadIdx.x & 31;
    if (warp >= nnodes) return;
    const int n = warp;
    const int s0 = g_rowstart[n];
    const int s1 = g_rowstart[n + 1];

    const float ad0 = g_adst[n * H];
    const float ad1 = (H == 2) ? g_adst[n * H + 1] : 0.f;

    // pass 1: segment max of leaky logits
    float m0 = -1e30f, m1 = -1e30f;
    for (int i = s0 + lane; i < s1; i += 32) {
        int s = g_csrc[i];
        float l0 = g_asrc[s * H] + ad0; l0 = l0 > 0.f ? l0 : 0.2f * l0;
        m0 = fmaxf(m0, l0);
        if (H == 2) {
            float l1 = g_asrc[s * H + 1] + ad1; l1 = l1 > 0.f ? l1 : 0.2f * l1;
            m1 = fmaxf(m1, l1);
        }
    }
#pragma unroll
    for (int o = 16; o; o >>= 1) {
        m0 = fmaxf(m0, __shfl_xor_sync(0xffffffffu, m0, o));
        if (H == 2) m1 = fmaxf(m1, __shfl_xor_sync(0xffffffffu, m1, o));
    }

    // pass 2: sum of exps + unnormalized message accumulation (float4)
    float sm0 = 0.f, sm1 = 0.f;
    float4 acc[V4];
#pragma unroll
    for (int j = 0; j < V4; j++) acc[j] = make_float4(0.f, 0.f, 0.f, 0.f);

    for (int base = s0; base < s1; base += 32) {
        int i = base + lane;
        int sv = 0; float w0 = 0.f, w1 = 0.f;
        if (i < s1) {
            sv = g_csrc[i];
            float l0 = g_asrc[sv * H] + ad0; l0 = l0 > 0.f ? l0 : 0.2f * l0;
            w0 = __expf(l0 - m0); sm0 += w0;
            if (H == 2) {
                float l1 = g_asrc[sv * H + 1] + ad1; l1 = l1 > 0.f ? l1 : 0.2f * l1;
                w1 = __expf(l1 - m1); sm1 += w1;
            }
        }
        int cnt = s1 - base; if (cnt > 32) cnt = 32;
#pragma unroll 4
        for (int t = 0; t < cnt; t++) {
            int   sb  = __shfl_sync(0xffffffffu, sv, t);
            float wb0 = __shfl_sync(0xffffffffu, w0, t);
            float wb1 = (H == 2) ? __shfl_sync(0xffffffffu, w1, t) : 0.f;
            const float4* row4 = (const float4*)(hbuf + (size_t)sb * HC);
#pragma unroll
            for (int j = 0; j < V4; j++) {
                int c4 = lane + j * 32;           // float4 index; column = c4*4
                if (HC >= 128 || c4 * 4 < HC) {
                    float wv = (H == 2) ? ((c4 * 4) < C ? wb0 : wb1) : wb0;
                    float4 hv = row4[c4];
                    acc[j].x += hv.x * wv;
                    acc[j].y += hv.y * wv;
                    acc[j].z += hv.z * wv;
                    acc[j].w += hv.w * wv;
                }
            }
        }
    }
#pragma unroll
    for (int o = 16; o; o >>= 1) {
        sm0 += __shfl_xor_sync(0xffffffffu, sm0, o);
        if (H == 2) sm1 += __shfl_xor_sync(0xffffffffu, sm1, o);
    }
    const float inv0 = 1.f / (sm0 + 1e-16f);
    const float inv1 = (H == 2) ? 1.f / (sm1 + 1e-16f) : 0.f;

    // pass 3: alpha writeback (original edge order)
    for (int i = s0 + lane; i < s1; i += 32) {
        int s = g_csrc[i];
        int e = g_eid[i];
        if (e < 0 || e >= nedges) continue;
        float l0 = g_asrc[s * H] + ad0; l0 = l0 > 0.f ? l0 : 0.2f * l0;
        alpha_out[(size_t)e * H] = __expf(l0 - m0) * inv0;
        if (H == 2) {
            float l1 = g_asrc[s * H + 1] + ad1; l1 = l1 > 0.f ? l1 : 0.2f * l1;
            alpha_out[(size_t)e * H + 1] = __expf(l1 - m1) * inv1;
        }
    }

    // epilogue: normalize, bias, optional relu
#pragma unroll
    for (int j = 0; j < V4; j++) {
        int c4 = lane + j * 32;
        int c = c4 * 4;
        if (HC >= 128 || c < HC) {
            float invv = (H == 2) ? (c < C ? inv0 : inv1) : inv0;
            float4 v;
            v.x = acc[j].x * invv + bias[c + 0];
            v.y = acc[j].y * invv + bias[c + 1];
            v.z = acc[j].z * invv + bias[c + 2];
            v.w = acc[j].w * invv + bias[c + 3];
            if (RELU) {
                v.x = fmaxf(v.x, 0.f); v.y = fmaxf(v.y, 0.f);
                v.z = fmaxf(v.z, 0.f); v.w = fmaxf(v.w, 0.f);
            }
            *(float4*)(outbuf + (size_t)n * HC + c) = v;
        }
    }
}

// ---------------------------------------------------------------------------
// Global mean pooling + classifier
// ---------------------------------------------------------------------------
__global__ void k_pool_init(float* __restrict__ gemb) {
    int t = threadIdx.x;
    if (t < 256) gemb[t] = 0.f;
    if (t < 16) g_cnt[t] = 0.f;
}

__global__ void k_pool(const int* __restrict__ batch, const float* __restrict__ emb,
                       float* __restrict__ gemb, int nnodes) {
    __shared__ float sh[256];
    __shared__ float shc[16];
    for (int i = threadIdx.x; i < 256; i += blockDim.x) sh[i] = 0.f;
    if (threadIdx.x < 16) shc[threadIdx.x] = 0.f;
    __syncthreads();
    int n = blockIdx.x * blockDim.x + threadIdx.x;
    if (n < nnodes) {
        int g = load_idx(batch, (size_t)n);
        g = g < 0 ? 0 : (g > 15 ? 15 : g);
        atomicAdd(&shc[g], 1.f);
        const float* row = emb + (size_t)n * 16;
#pragma unroll
        for (int c = 0; c < 16; c++) atomicAdd(&sh[g * 16 + c], row[c]);
    }
    __syncthreads();
    for (int i = threadIdx.x; i < 256; i += blockDim.x)
        if (sh[i] != 0.f) atomicAdd(&gemb[i], sh[i]);
    if (threadIdx.x < 16 && shc[threadIdx.x] != 0.f)
        atomicAdd(&g_cnt[threadIdx.x], shc[threadIdx.x]);
}

__global__ void k_final(const float* __restrict__ Wl, const float* __restrict__ bl,
                        float* __restrict__ gemb, float* __restrict__ logits) {
    __shared__ float ge[256];
    int t = threadIdx.x;
    if (t < 256) {
        int g = t >> 4;
        float cnt = g_cnt[g]; if (cnt < 1.f) cnt = 1.f;
        float v = gemb[t] / cnt;
        gemb[t] = v;   // normalized g_emb output
        ge[t] = v;
    }
    __syncthreads();
    if (t < 32) {
        int g = t >> 1, j = t & 1;
        float s = bl[j];
#pragma unroll
        for (int c = 0; c < 16; c++) s += ge[g * 16 + c] * Wl[c * 2 + j];
        logits[t] = s;  // final logits
    }
}

// ---------------------------------------------------------------------------
// Orchestration.  CSR build runs on a side stream, overlapped with GEMM1
// (which is independent of the graph structure). Fork/join via events —
// graph-capture-safe, no allocations.
// ---------------------------------------------------------------------------
extern "C" void kernel_launch(void* const* d_in, const int* in_sizes, int n_in,
                              void* d_out, int out_size) {
    int ix, iei, ib, iW1, ias1, iad1, ib1, iW2, ias2, iad2, ib2,
        iW3, ias3, iad3, ib3, iWl, ibl;
    if (in_sizes[0] > 1000000) {  // x first => insertion order
        ix = 0; iei = 1; ib = 2;
        iW1 = 3;  ias1 = 4;  iad1 = 5;  ib1 = 6;
        iW2 = 7;  ias2 = 8;  iad2 = 9;  ib2 = 10;
        iW3 = 11; ias3 = 12; iad3 = 13; ib3 = 14;
        iWl = 15; ibl = 16;
    } else {                       // alphabetical order
        iW1 = 0; iW2 = 1; iW3 = 2; iWl = 3;
        iad1 = 4; iad2 = 5; iad3 = 6;
        ias1 = 7; ias2 = 8; ias3 = 9;
        ib1 = 10; ib2 = 11; ib3 = 12;
        ib = 13; ibl = 14; iei = 15; ix = 16;
    }

    const float* x     = (const float*)d_in[ix];
    const int*   ei    = (const int*)d_in[iei];
    const int*   batch = (const int*)d_in[ib];
    const float* W1 = (const float*)d_in[iW1];
    const float* as1 = (const float*)d_in[ias1];
    const float* ad1 = (const float*)d_in[iad1];
    const float* b1  = (const float*)d_in[ib1];
    const float* W2 = (const float*)d_in[iW2];
    const float* as2 = (const float*)d_in[ias2];
    const float* ad2 = (const float*)d_in[iad2];
    const float* b2  = (const float*)d_in[ib2];
    const float* W3 = (const float*)d_in[iW3];
    const float* as3 = (const float*)d_in[ias3];
    const float* ad3 = (const float*)d_in[iad3];
    const float* b3  = (const float*)d_in[ib3];
    const float* Wl = (const float*)d_in[iWl];
    const float* bl = (const float*)d_in[ibl];
    float* out = (float*)d_out;

    int N = in_sizes[ix] / 128;
    int E = in_sizes[iei] / 2;
    if (N > NMAX) N = NMAX;
    if (E > EMAX) E = EMAX;

    void* tmp;
    cudaGetSymbolAddress(&tmp, g_h);      float* h      = (float*)tmp;
    cudaGetSymbolAddress(&tmp, g_feat);   float* feat   = (float*)tmp;
    cudaGetSymbolAddress(&tmp, g_embS);   float* embS   = (float*)tmp;
    cudaGetSymbolAddress(&tmp, g_alphaS); float* alphaS = (float*)tmp;
    cudaGetSymbolAddress(&tmp, g_gembS);  float* gembS  = (float*)tmp;

    // output layout: logits[16,2] | g_emb[16,16] | emb[N,16] | a1[E,2] | a2[E] | a3[E]
    size_t oGemb = 32;
    size_t oEmb  = oGemb + 256;
    size_t oA1   = oEmb + (size_t)N * 16;
    size_t oA2   = oA1 + (size_t)E * 2;
    size_t oA3   = oA2 + (size_t)E;
    size_t FULL  = oA3 + (size_t)E;
    size_t osz = (size_t)out_size;
    float* OUT_gemb = (osz >= oEmb)  ? out + oGemb : gembS;
    float* OUT_emb  = (osz >= oA1)   ? out + oEmb  : embS;
    float* OUT_a1   = (osz >= oA2)   ? out + oA1   : alphaS;
    float* OUT_a2   = (osz >= oA3)   ? out + oA2   : alphaS;
    float* OUT_a3   = (osz >= FULL)  ? out + oA3   : alphaS;

    const int TB = 256;
    const int nb = (N + 1023) / 1024;              // scan blocks
    const int gemmBlocks = (N + 127) / 128;
    const int warpBlocksN = (N + 7) / 8;           // 1 warp per node

    // ---- fork/join setup (created + destroyed every call: deterministic) ----
    cudaStream_t s2 = 0;
    cudaEvent_t evFork = 0, evJoin = 0;
    bool forked =
        (cudaStreamCreateWithFlags(&s2, cudaStreamNonBlocking) == cudaSuccess) &&
        (cudaEventCreateWithFlags(&evFork, cudaEventDisableTiming) == cudaSuccess) &&
        (cudaEventCreateWithFlags(&evJoin, cudaEventDisableTiming) == cudaSuccess);
    cudaStream_t sc = forked ? s2 : 0;   // CSR chain stream

    // launch 0: width detection (needed by CSR chain)
    k_detect_width<<<1, 1>>>(ei);

    if (forked) {
        cudaEventRecord(evFork, 0);
        cudaStreamWaitEvent(sc, evFork, 0);
    }

    // ---- CSR chain on side stream; GEMM1 concurrently on main stream ----
    k_zero_deg<<<(N + TB - 1) / TB, TB, 0, sc>>>(N);                 // launch 1
    k_hist<<<(E + TB - 1) / TB, TB, 0, sc>>>(ei, E, N);              // launch 2
    k_gemm128<2><<<gemmBlocks, TB>>>(x, W1, as1, ad1, h, N);         // launch 3 (main)
    k_scan_local<<<nb, 1024, 0, sc>>>(N);                            // launch 4
    k_scan_bsum<<<1, NBMAX, 0, sc>>>(nb, N);
    k_scan_add<<<nb, 1024, 0, sc>>>(N);
    k_scatter<<<(E + TB - 1) / TB, TB, 0, sc>>>(ei, E, N);
    k_pool_init<<<1, 256, 0, sc>>>(OUT_gemb);

    if (forked) {
        cudaEventRecord(evJoin, sc);
        cudaStreamWaitEvent(0, evJoin, 0);
    }

    // ---- Layer 1 aggregate (needs CSR + gemm1) ----
    k_aggregate<2, 64, true><<<warpBlocksN, TB>>>(h, b1, feat, OUT_a1, N, E);

    // ---- Layer 2: 128 -> (1 head x 128), +b2, relu ----
    k_gemm128<1><<<gemmBlocks, TB>>>(feat, W2, as2, ad2, h, N);
    k_aggregate<1, 128, true><<<warpBlocksN, TB>>>(h, b2, feat, OUT_a2, N, E);

    // ---- Layer 3: 128 -> (1 head x 16), +b3 ----
    k_gemm16<<<((size_t)N * 16 + TB - 1) / TB, TB>>>(feat, W3, as3, ad3, h, N);
    k_aggregate<1, 16, false><<<warpBlocksN, TB>>>(h, b3, OUT_emb, OUT_a3, N, E);

    // ---- Global mean pool + classifier ----
    k_pool<<<(N + TB - 1) / TB, TB>>>(batch, OUT_emb, OUT_gemb, N);
    k_final<<<1, 256>>>(Wl, bl, OUT_gemb, out);

    if (evFork) cudaEventDestroy(evFork);
    if (evJoin) cudaEventDestroy(evJoin);
    if (s2) cudaStreamDestroy(s2);
}

// round 11
// speedup vs baseline: 1.2806x; 1.0172x over previous
#include <cuda_runtime.h>
#include <cstdint>
#include <cstddef>

// ---------------------------------------------------------------------------
// Problem constants (match reference_code)
// ---------------------------------------------------------------------------
static constexpr int NMAX = 50000;    // nodes
static constexpr int EMAX = 850000;   // edges (800k random + 50k self loops)
static constexpr int NBMAX = 64;      // max scan blocks (ceil(50000/1024)=49)

// ---------------------------------------------------------------------------
// Scratch (static __device__ globals — no allocation allowed)
// ---------------------------------------------------------------------------
static __device__ __align__(16) float g_h[(size_t)NMAX * 128];     // pre-agg features
static __device__ __align__(16) float g_feat[(size_t)NMAX * 128];  // post-layer features
static __device__ float g_asrc[(size_t)NMAX * 2];
static __device__ float g_adst[(size_t)NMAX * 2];
static __device__ float g_apS[(size_t)NMAX * 2];     // partial alpha dots (H=1 split)
static __device__ float g_apD[(size_t)NMAX * 2];
static __device__ int   g_deg[NMAX];                 // histogram, then cursor
static __device__ int   g_rowstart[NMAX + 1];
static __device__ int   g_bsum[NBMAX];
static __device__ int   g_csrc[EMAX];                // src sorted by dst
static __device__ int   g_eid[EMAX];                 // original edge id
static __device__ float g_cnt[16];
static __device__ int   g_is64;                      // 1 if index buffers are int64
// fallback scratch if d_out is smaller than the full flattened tuple
static __device__ __align__(16) float g_embS[(size_t)NMAX * 16];
static __device__ __align__(16) float g_alphaS[(size_t)EMAX * 2];
static __device__ float g_gembS[256];

// ---------------------------------------------------------------------------
// Index width detection + decode (int32 vs int64 little-endian, values small)
// ---------------------------------------------------------------------------
__global__ void k_detect_width(const int* __restrict__ w) {
    int z = 0;
#pragma unroll
    for (int k = 0; k < 8; k++) z |= w[2 * k + 1];
    g_is64 = (z == 0) ? 1 : 0;
}

__device__ __forceinline__ int load_idx(const int* __restrict__ w, size_t i) {
    return g_is64 ? w[2 * i] : w[i];
}

// ---------------------------------------------------------------------------
// CSR build
// ---------------------------------------------------------------------------
__global__ void k_zero_deg(int n) {
    int i = blockIdx.x * blockDim.x + threadIdx.x;
    if (i < n) g_deg[i] = 0;
}

__global__ void k_hist(const int* __restrict__ ei, int E, int n) {
    int e = blockIdx.x * blockDim.x + threadIdx.x;
    if (e >= E) return;
    int d = load_idx(ei, (size_t)E + e);
    d = d < 0 ? 0 : (d >= n ? n - 1 : d);
    atomicAdd(&g_deg[d], 1);
}

__global__ void k_scan_local(int n) {
    __shared__ int sh[1024];
    const int b = blockIdx.x, t = threadIdx.x;
    const int i = b * 1024 + t;
    int v = (i < n) ? g_deg[i] : 0;
    if (i < n) g_deg[i] = 0;
    sh[t] = v;
    __syncthreads();
    for (int off = 1; off < 1024; off <<= 1) {
        int tv = (t >= off) ? sh[t - off] : 0;
        __syncthreads();
        sh[t] += tv;
        __syncthreads();
    }
    if (i < n) g_rowstart[i] = sh[t] - v;   // exclusive, local to block
    if (t == 1023) g_bsum[b] = sh[1023];
}

__global__ void k_scan_bsum(int nb, int n) {
    __shared__ int sh[NBMAX];
    int t = threadIdx.x;
    int v = (t < nb) ? g_bsum[t] : 0;
    sh[t] = v;
    __syncthreads();
    for (int off = 1; off < NBMAX; off <<= 1) {
        int tv = (t >= off) ? sh[t - off] : 0;
        __syncthreads();
        sh[t] += tv;
        __syncthreads();
    }
    if (t < nb) g_bsum[t] = sh[t] - v;
    if (t == nb - 1) g_rowstart[n] = sh[t];
}

__global__ void k_scan_add(int n) {
    int i = blockIdx.x * 1024 + threadIdx.x;
    if (i < n) g_rowstart[i] += g_bsum[blockIdx.x];
}

__global__ void k_scatter(const int* __restrict__ ei, int E, int n) {
    int e = blockIdx.x * blockDim.x + threadIdx.x;
    if (e >= E) return;
    int d = load_idx(ei, (size_t)E + e);
    d = d < 0 ? 0 : (d >= n ? n - 1 : d);
    int s = load_idx(ei, (size_t)e);
    s = s < 0 ? 0 : (s >= n ? n - 1 : s);
    int pos = g_rowstart[d] + atomicAdd(&g_deg[d], 1);
    if (pos < EMAX) { g_csrc[pos] = s; g_eid[pos] = e; }
}

// ---------------------------------------------------------------------------
// GEMM + fused alpha epilogue.  BM=128, BN=64, BK=8, 256 thr, 8x4 micro-tile,
// 3 CTAs/SM target. Grid (rows/128, 2): blockIdx.y selects column half.
// H=2: column half == head; alpha writes are final (g_asrc/g_adst).
// H=1: alpha dot spans both halves; writes partials (g_apS/g_apD), combined
//      by k_combine afterwards.
// ---------------------------------------------------------------------------
template <int H>
__global__ __launch_bounds__(256, 3) void k_gemm64n(
        const float* __restrict__ A, const float* __restrict__ B,
        const float* __restrict__ avs, const float* __restrict__ avd,
        float* __restrict__ Cm, float* __restrict__ aoutS,
        float* __restrict__ aoutD, int nrows) {
    __shared__ float Ast[2][8][132];   // transposed A tile [buf][k][m]
    __shared__ float Bs[2][8][68];
    const int tid = threadIdx.x;
    const int n0 = blockIdx.x * 128;
    const int c0 = blockIdx.y * 64;
    const int ar = tid >> 1, akq = (tid & 1) << 2;   // A load: row, k-quad
    const int bk = tid >> 4, bq = (tid & 15) << 2;   // B load (tid<128): k-row, col-quad
    const bool bload = tid < 128;
    const int tx = tid & 15, ty = tid >> 4;          // micro-tile coords
    const int gr = n0 + ar;

    float acc[8][4];
#pragma unroll
    for (int i = 0; i < 8; i++)
#pragma unroll
        for (int j = 0; j < 4; j++) acc[i][j] = 0.f;

    // prologue: stage 0
    {
        float4 av = make_float4(0.f, 0.f, 0.f, 0.f);
        if (gr < nrows) av = *(const float4*)(A + (size_t)gr * 128 + akq);
        Ast[0][akq + 0][ar] = av.x;
        Ast[0][akq + 1][ar] = av.y;
        Ast[0][akq + 2][ar] = av.z;
        Ast[0][akq + 3][ar] = av.w;
        if (bload) {
            float4 bv = *(const float4*)(B + (size_t)bk * 128 + c0 + bq);
            *(float4*)(&Bs[0][bk][bq]) = bv;
        }
    }
    __syncthreads();

    for (int kt = 0; kt < 128; kt += 8) {
        const int cur = (kt >> 3) & 1;
        const bool more = (kt + 8) < 128;
        float4 av2 = make_float4(0.f, 0.f, 0.f, 0.f), bv2;
        if (more) {
            if (gr < nrows) av2 = *(const float4*)(A + (size_t)gr * 128 + kt + 8 + akq);
            if (bload) bv2 = *(const float4*)(B + (size_t)(kt + 8 + bk) * 128 + c0 + bq);
        }
#pragma unroll
        for (int k = 0; k < 8; k++) {
            float4 a0 = *(const float4*)(&Ast[cur][k][ty << 3]);
            float4 a1 = *(const float4*)(&Ast[cur][k][(ty << 3) + 4]);
            float4 b  = *(const float4*)(&Bs[cur][k][tx << 2]);
            float am[8] = {a0.x, a0.y, a0.z, a0.w, a1.x, a1.y, a1.z, a1.w};
#pragma unroll
            for (int i = 0; i < 8; i++) {
                acc[i][0] += am[i] * b.x;
                acc[i][1] += am[i] * b.y;
                acc[i][2] += am[i] * b.z;
                acc[i][3] += am[i] * b.w;
            }
        }
        if (more) {
            const int nxt = cur ^ 1;
            Ast[nxt][akq + 0][ar] = av2.x;
            Ast[nxt][akq + 1][ar] = av2.y;
            Ast[nxt][akq + 2][ar] = av2.z;
            Ast[nxt][akq + 3][ar] = av2.w;
            if (bload) *(float4*)(&Bs[nxt][bk][bq]) = bv2;
        }
        __syncthreads();
    }

    // fused alpha epilogue.
    // H=2: head = blockIdx.y, within-head col = tx*4  -> avs + y*64 + tx*4
    // H=1: global col = c0 + tx*4 = y*64 + tx*4        -> same expression
    float4 as4 = *(const float4*)(avs + blockIdx.y * 64 + (tx << 2));
    float4 ad4 = *(const float4*)(avd + blockIdx.y * 64 + (tx << 2));

#pragma unroll
    for (int i = 0; i < 8; i++) {
        const int row = n0 + (ty << 3) + i;
        float ps = acc[i][0] * as4.x + acc[i][1] * as4.y +
                   acc[i][2] * as4.z + acc[i][3] * as4.w;
        float pd = acc[i][0] * ad4.x + acc[i][1] * ad4.y +
                   acc[i][2] * ad4.z + acc[i][3] * ad4.w;
        // reduce over the 16 tx lanes (xor stays within each 16-lane half)
#pragma unroll
        for (int o = 8; o; o >>= 1) {
            ps += __shfl_xor_sync(0xffffffffu, ps, o);
            pd += __shfl_xor_sync(0xffffffffu, pd, o);
        }
        if (tx == 0 && row < nrows) {
            aoutS[row * 2 + blockIdx.y] = ps;   // H=2: final (head=y); H=1: partial
            aoutD[row * 2 + blockIdx.y] = pd;
        }
        if (row < nrows) {
            float4 v = {acc[i][0], acc[i][1], acc[i][2], acc[i][3]};
            *(float4*)(Cm + (size_t)row * 128 + c0 + (tx << 2)) = v;
        }
    }
}

// Combine the two column-half partial alpha dots (H=1 layers).
__global__ void k_combine(int n) {
    int i = blockIdx.x * blockDim.x + threadIdx.x;
    if (i < n) {
        g_asrc[i] = g_apS[2 * i] + g_apS[2 * i + 1];
        g_adst[i] = g_apD[2 * i] + g_apD[2 * i + 1];
    }
}

// Small GEMM for layer 3 ([N,128] @ [128,16]) + fused alpha (H=1, C=16).
__global__ void k_gemm16(const float* __restrict__ A, const float* __restrict__ B,
                         const float* __restrict__ avs, const float* __restrict__ avd,
                         float* __restrict__ Cm, int nrows) {
    __shared__ float Bsm[128 * 16];
    for (int i = threadIdx.x; i < 128 * 16; i += blockDim.x) Bsm[i] = B[i];
    __syncthreads();
    int idx = blockIdx.x * blockDim.x + threadIdx.x;
    int n = idx >> 4, c = idx & 15;
    float s = 0.f;
    if (n < nrows) {
        const float* a = A + (size_t)n * 128;
#pragma unroll
        for (int k = 0; k < 128; k++) s += a[k] * Bsm[k * 16 + c];
    }
    float ps = s * avs[c];
    float pd = s * avd[c];
#pragma unroll
    for (int o = 8; o; o >>= 1) {
        ps += __shfl_xor_sync(0xffffffffu, ps, o);
        pd += __shfl_xor_sync(0xffffffffu, pd, o);
    }
    if (n < nrows) {
        Cm[(size_t)n * 16 + c] = s;
        if (c == 0) { g_asrc[n] = ps; g_adst[n] = pd; }
    }
}

// ---------------------------------------------------------------------------
// Fused per-node softmax + aggregation (gather over dst-CSR). One warp/node.
// ---------------------------------------------------------------------------
template <int H, int C, bool RELU>
__global__ void k_aggregate(const float* __restrict__ hbuf, const float* __restrict__ bias,
                            float* __restrict__ outbuf, float* __restrict__ alpha_out,
                            int nnodes, int nedges) {
    constexpr int HC = H * C;
    constexpr int V4 = (HC + 127) / 128;   // float4 chunks per lane
    const int warp = (blockIdx.x * blockDim.x + threadIdx.x) >> 5;
    const int lane = threadIdx.x & 31;
    if (warp >= nnodes) return;
    const int n = warp;
    const int s0 = g_rowstart[n];
    const int s1 = g_rowstart[n + 1];

    const float ad0 = g_adst[n * H];
    const float ad1 = (H == 2) ? g_adst[n * H + 1] : 0.f;

    // pass 1: segment max of leaky logits
    float m0 = -1e30f, m1 = -1e30f;
    for (int i = s0 + lane; i < s1; i += 32) {
        int s = g_csrc[i];
        float l0 = g_asrc[s * H] + ad0; l0 = l0 > 0.f ? l0 : 0.2f * l0;
        m0 = fmaxf(m0, l0);
        if (H == 2) {
            float l1 = g_asrc[s * H + 1] + ad1; l1 = l1 > 0.f ? l1 : 0.2f * l1;
            m1 = fmaxf(m1, l1);
        }
    }
#pragma unroll
    for (int o = 16; o; o >>= 1) {
        m0 = fmaxf(m0, __shfl_xor_sync(0xffffffffu, m0, o));
        if (H == 2) m1 = fmaxf(m1, __shfl_xor_sync(0xffffffffu, m1, o));
    }

    // pass 2: sum of exps + unnormalized message accumulation (float4)
    float sm0 = 0.f, sm1 = 0.f;
    float4 acc[V4];
#pragma unroll
    for (int j = 0; j < V4; j++) acc[j] = make_float4(0.f, 0.f, 0.f, 0.f);

    for (int base = s0; base < s1; base += 32) {
        int i = base + lane;
        int sv = 0; float w0 = 0.f, w1 = 0.f;
        if (i < s1) {
            sv = g_csrc[i];
            float l0 = g_asrc[sv * H] + ad0; l0 = l0 > 0.f ? l0 : 0.2f * l0;
            w0 = __expf(l0 - m0); sm0 += w0;
            if (H == 2) {
                float l1 = g_asrc[sv * H + 1] + ad1; l1 = l1 > 0.f ? l1 : 0.2f * l1;
                w1 = __expf(l1 - m1); sm1 += w1;
            }
        }
        int cnt = s1 - base; if (cnt > 32) cnt = 32;
#pragma unroll 4
        for (int t = 0; t < cnt; t++) {
            int   sb  = __shfl_sync(0xffffffffu, sv, t);
            float wb0 = __shfl_sync(0xffffffffu, w0, t);
            float wb1 = (H == 2) ? __shfl_sync(0xffffffffu, w1, t) : 0.f;
            const float4* row4 = (const float4*)(hbuf + (size_t)sb * HC);
#pragma unroll
            for (int j = 0; j < V4; j++) {
                int c4 = lane + j * 32;           // float4 index; column = c4*4
                if (HC >= 128 || c4 * 4 < HC) {
                    float wv = (H == 2) ? ((c4 * 4) < C ? wb0 : wb1) : wb0;
                    float4 hv = row4[c4];
                    acc[j].x += hv.x * wv;
                    acc[j].y += hv.y * wv;
                    acc[j].z += hv.z * wv;
                    acc[j].w += hv.w * wv;
                }
            }
        }
    }
#pragma unroll
    for (int o = 16; o; o >>= 1) {
        sm0 += __shfl_xor_sync(0xffffffffu, sm0, o);
        if (H == 2) sm1 += __shfl_xor_sync(0xffffffffu, sm1, o);
    }
    const float inv0 = 1.f / (sm0 + 1e-16f);
    const float inv1 = (H == 2) ? 1.f / (sm1 + 1e-16f) : 0.f;

    // pass 3: alpha writeback (original edge order)
    for (int i = s0 + lane; i < s1; i += 32) {
        int s = g_csrc[i];
        int e = g_eid[i];
        if (e < 0 || e >= nedges) continue;
        float l0 = g_asrc[s * H] + ad0; l0 = l0 > 0.f ? l0 : 0.2f * l0;
        alpha_out[(size_t)e * H] = __expf(l0 - m0) * inv0;
        if (H == 2) {
            float l1 = g_asrc[s * H + 1] + ad1; l1 = l1 > 0.f ? l1 : 0.2f * l1;
            alpha_out[(size_t)e * H + 1] = __expf(l1 - m1) * inv1;
        }
    }

    // epilogue: normalize, bias, optional relu
#pragma unroll
    for (int j = 0; j < V4; j++) {
        int c4 = lane + j * 32;
        int c = c4 * 4;
        if (HC >= 128 || c < HC) {
            float invv = (H == 2) ? (c < C ? inv0 : inv1) : inv0;
            float4 v;
            v.x = acc[j].x * invv + bias[c + 0];
            v.y = acc[j].y * invv + bias[c + 1];
            v.z = acc[j].z * invv + bias[c + 2];
            v.w = acc[j].w * invv + bias[c + 3];
            if (RELU) {
                v.x = fmaxf(v.x, 0.f); v.y = fmaxf(v.y, 0.f);
                v.z = fmaxf(v.z, 0.f); v.w = fmaxf(v.w, 0.f);
            }
            *(float4*)(outbuf + (size_t)n * HC + c) = v;
        }
    }
}

// ---------------------------------------------------------------------------
// Global mean pooling + classifier
// ---------------------------------------------------------------------------
__global__ void k_pool_init(float* __restrict__ gemb) {
    int t = threadIdx.x;
    if (t < 256) gemb[t] = 0.f;
    if (t < 16) g_cnt[t] = 0.f;
}

__global__ void k_pool(const int* __restrict__ batch, const float* __restrict__ emb,
                       float* __restrict__ gemb, int nnodes) {
    __shared__ float sh[256];
    __shared__ float shc[16];
    for (int i = threadIdx.x; i < 256; i += blockDim.x) sh[i] = 0.f;
    if (threadIdx.x < 16) shc[threadIdx.x] = 0.f;
    __syncthreads();
    int n = blockIdx.x * blockDim.x + threadIdx.x;
    if (n < nnodes) {
        int g = load_idx(batch, (size_t)n);
        g = g < 0 ? 0 : (g > 15 ? 15 : g);
        atomicAdd(&shc[g], 1.f);
        const float* row = emb + (size_t)n * 16;
#pragma unroll
        for (int c = 0; c < 16; c++) atomicAdd(&sh[g * 16 + c], row[c]);
    }
    __syncthreads();
    for (int i = threadIdx.x; i < 256; i += blockDim.x)
        if (sh[i] != 0.f) atomicAdd(&gemb[i], sh[i]);
    if (threadIdx.x < 16 && shc[threadIdx.x] != 0.f)
        atomicAdd(&g_cnt[threadIdx.x], shc[threadIdx.x]);
}

__global__ void k_final(const float* __restrict__ Wl, const float* __restrict__ bl,
                        float* __restrict__ gemb, float* __restrict__ logits) {
    __shared__ float ge[256];
    int t = threadIdx.x;
    if (t < 256) {
        int g = t >> 4;
        float cnt = g_cnt[g]; if (cnt < 1.f) cnt = 1.f;
        float v = gemb[t] / cnt;
        gemb[t] = v;   // normalized g_emb output
        ge[t] = v;
    }
    __syncthreads();
    if (t < 32) {
        int g = t >> 1, j = t & 1;
        float s = bl[j];
#pragma unroll
        for (int c = 0; c < 16; c++) s += ge[g * 16 + c] * Wl[c * 2 + j];
        logits[t] = s;  // final logits
    }
}

// ---------------------------------------------------------------------------
// Orchestration.  CSR build on a side stream overlapped with GEMM1.
// ---------------------------------------------------------------------------
extern "C" void kernel_launch(void* const* d_in, const int* in_sizes, int n_in,
                              void* d_out, int out_size) {
    int ix, iei, ib, iW1, ias1, iad1, ib1, iW2, ias2, iad2, ib2,
        iW3, ias3, iad3, ib3, iWl, ibl;
    if (in_sizes[0] > 1000000) {  // x first => insertion order
        ix = 0; iei = 1; ib = 2;
        iW1 = 3;  ias1 = 4;  iad1 = 5;  ib1 = 6;
        iW2 = 7;  ias2 = 8;  iad2 = 9;  ib2 = 10;
        iW3 = 11; ias3 = 12; iad3 = 13; ib3 = 14;
        iWl = 15; ibl = 16;
    } else {                       // alphabetical order
        iW1 = 0; iW2 = 1; iW3 = 2; iWl = 3;
        iad1 = 4; iad2 = 5; iad3 = 6;
        ias1 = 7; ias2 = 8; ias3 = 9;
        ib1 = 10; ib2 = 11; ib3 = 12;
        ib = 13; ibl = 14; iei = 15; ix = 16;
    }

    const float* x     = (const float*)d_in[ix];
    const int*   ei    = (const int*)d_in[iei];
    const int*   batch = (const int*)d_in[ib];
    const float* W1 = (const float*)d_in[iW1];
    const float* as1 = (const float*)d_in[ias1];
    const float* ad1 = (const float*)d_in[iad1];
    const float* b1  = (const float*)d_in[ib1];
    const float* W2 = (const float*)d_in[iW2];
    const float* as2 = (const float*)d_in[ias2];
    const float* ad2 = (const float*)d_in[iad2];
    const float* b2  = (const float*)d_in[ib2];
    const float* W3 = (const float*)d_in[iW3];
    const float* as3 = (const float*)d_in[ias3];
    const float* ad3 = (const float*)d_in[iad3];
    const float* b3  = (const float*)d_in[ib3];
    const float* Wl = (const float*)d_in[iWl];
    const float* bl = (const float*)d_in[ibl];
    float* out = (float*)d_out;

    int N = in_sizes[ix] / 128;
    int E = in_sizes[iei] / 2;
    if (N > NMAX) N = NMAX;
    if (E > EMAX) E = EMAX;

    void* tmp;
    cudaGetSymbolAddress(&tmp, g_h);      float* h      = (float*)tmp;
    cudaGetSymbolAddress(&tmp, g_feat);   float* feat   = (float*)tmp;
    cudaGetSymbolAddress(&tmp, g_asrc);   float* asrcP  = (float*)tmp;
    cudaGetSymbolAddress(&tmp, g_adst);   float* adstP  = (float*)tmp;
    cudaGetSymbolAddress(&tmp, g_apS);    float* apSP   = (float*)tmp;
    cudaGetSymbolAddress(&tmp, g_apD);    float* apDP   = (float*)tmp;
    cudaGetSymbolAddress(&tmp, g_embS);   float* embS   = (float*)tmp;
    cudaGetSymbolAddress(&tmp, g_alphaS); float* alphaS = (float*)tmp;
    cudaGetSymbolAddress(&tmp, g_gembS);  float* gembS  = (float*)tmp;

    // output layout: logits[16,2] | g_emb[16,16] | emb[N,16] | a1[E,2] | a2[E] | a3[E]
    size_t oGemb = 32;
    size_t oEmb  = oGemb + 256;
    size_t oA1   = oEmb + (size_t)N * 16;
    size_t oA2   = oA1 + (size_t)E * 2;
    size_t oA3   = oA2 + (size_t)E;
    size_t FULL  = oA3 + (size_t)E;
    size_t osz = (size_t)out_size;
    float* OUT_gemb = (osz >= oEmb)  ? out + oGemb : gembS;
    float* OUT_emb  = (osz >= oA1)   ? out + oEmb  : embS;
    float* OUT_a1   = (osz >= oA2)   ? out + oA1   : alphaS;
    float* OUT_a2   = (osz >= oA3)   ? out + oA2   : alphaS;
    float* OUT_a3   = (osz >= FULL)  ? out + oA3   : alphaS;

    const int TB = 256;
    const int nb = (N + 1023) / 1024;              // scan blocks
    const dim3 gemmGrid((N + 127) / 128, 2);
    const int warpBlocksN = (N + 7) / 8;           // 1 warp per node

    // ---- fork/join setup ----
    cudaStream_t s2 = 0;
    cudaEvent_t evFork = 0, evJoin = 0;
    bool forked =
        (cudaStreamCreateWithFlags(&s2, cudaStreamNonBlocking) == cudaSuccess) &&
        (cudaEventCreateWithFlags(&evFork, cudaEventDisableTiming) == cudaSuccess) &&
        (cudaEventCreateWithFlags(&evJoin, cudaEventDisableTiming) == cudaSuccess);
    cudaStream_t sc = forked ? s2 : 0;   // CSR chain stream

    k_detect_width<<<1, 1>>>(ei);

    if (forked) {
        cudaEventRecord(evFork, 0);
        cudaStreamWaitEvent(sc, evFork, 0);
    }

    // ---- CSR chain on side stream; GEMM1 concurrently on main stream ----
    k_zero_deg<<<(N + TB - 1) / TB, TB, 0, sc>>>(N);
    k_hist<<<(E + TB - 1) / TB, TB, 0, sc>>>(ei, E, N);
    k_gemm64n<2><<<gemmGrid, TB>>>(x, W1, as1, ad1, h, asrcP, adstP, N);  // main
    k_scan_local<<<nb, 1024, 0, sc>>>(N);
    k_scan_bsum<<<1, NBMAX, 0, sc>>>(nb, N);
    k_scan_add<<<nb, 1024, 0, sc>>>(N);
    k_scatter<<<(E + TB - 1) / TB, TB, 0, sc>>>(ei, E, N);
    k_pool_init<<<1, 256, 0, sc>>>(OUT_gemb);

    if (forked) {
        cudaEventRecord(evJoin, sc);
        cudaStreamWaitEvent(0, evJoin, 0);
    }

    // ---- Layer 1 aggregate (needs CSR + gemm1) ----
    k_aggregate<2, 64, true><<<warpBlocksN, TB>>>(h, b1, feat, OUT_a1, N, E);

    // ---- Layer 2: 128 -> (1 head x 128), +b2, relu ----
    k_gemm64n<1><<<gemmGrid, TB>>>(feat, W2, as2, ad2, h, apSP, apDP, N);
    k_combine<<<(N + TB - 1) / TB, TB>>>(N);
    k_aggregate<1, 128, true><<<warpBlocksN, TB>>>(h, b2, feat, OUT_a2, N, E);

    // ---- Layer 3: 128 -> (1 head x 16), +b3 ----
    k_gemm16<<<((size_t)N * 16 + TB - 1) / TB, TB>>>(feat, W3, as3, ad3, h, N);
    k_aggregate<1, 16, false><<<warpBlocksN, TB>>>(h, b3, OUT_emb, OUT_a3, N, E);

    // ---- Global mean pool + classifier ----
    k_pool<<<(N + TB - 1) / TB, TB>>>(batch, OUT_emb, OUT_gemb, N);
    k_final<<<1, 256>>>(Wl, bl, OUT_gemb, out);

    if (evFork) cudaEventDestroy(evFork);
    if (evJoin) cudaEventDestroy(evJoin);
    if (s2) cudaStreamDestroy(s2);
}